// round 2
// baseline (speedup 1.0000x reference)
#include <cuda_runtime.h>
#include <math.h>

#define N_NODES 20000
#define N_EDGES 320000
#define HDIM 128
#define FIN 162

// ---------------- device scratch (static, no allocation) ----------------
__device__ float g_cf0[N_NODES * HDIM];
__device__ float g_cf1[N_NODES * HDIM];
__device__ float g_P[N_NODES * 2 * HDIM];

__device__ int   g_deg[N_NODES];
__device__ int   g_off[N_NODES];
__device__ int   g_pos[N_NODES];
__device__ int   g_toS[N_EDGES];
__device__ float4 g_efS[N_EDGES];

// col-max key slots: 0,1,2 = parent feats per iter; 3 = skip max; 4 = cg max
__device__ unsigned g_keys[5 * 128];

// packed / transposed weights
__device__ float g_WopT[FIN * 128];      // [k][c]
__device__ float g_WpT0[128 * 256];      // [k][c2]  (Wa|Wb iter0)
__device__ float g_WpT1[128 * 256];
__device__ float g_WeP0[128 * 4];        // [c][t]
__device__ float g_WeP1[128 * 4];
__device__ float g_WskipT[128 * 128];
__device__ float g_WgeoT[128 * 128];
__device__ float g_W2T[384 * 128];       // second_w transposed [j][c]
__device__ float g_WgT[128 * 128];       // second_geo_w transposed [j][c]

// ---------------- helpers ----------------
__device__ __forceinline__ unsigned fkey(float f) {
    unsigned u = __float_as_uint(f);
    return (u & 0x80000000u) ? ~u : (u | 0x80000000u);
}
__device__ __forceinline__ float fdec(unsigned k) {
    unsigned u = (k & 0x80000000u) ? (k & 0x7fffffffu) : ~k;
    return __uint_as_float(u);
}
__device__ __forceinline__ float leaky(float x) { return fmaxf(x, 0.01f * x); }

// ---------------- init ----------------
__global__ void k_init() {
    int i = blockIdx.x * 256 + threadIdx.x;
    if (i < N_NODES) g_deg[i] = 0;
    if (i < 5 * 128) g_keys[i] = fkey(-3.402823466e38f);
}

// ---------------- weight pack / transpose ----------------
__global__ void k_prep(const float* __restrict__ wop, const float* __restrict__ ew,
                       const float* __restrict__ wskip, const float* __restrict__ wgeo,
                       const float* __restrict__ w2, const float* __restrict__ wg2) {
    int i = blockIdx.x * 256 + threadIdx.x;
    const int A = FIN * 128;
    const int B = 2 * 128 * 256;
    const int C = 2 * 128 * 4;
    const int D = 128 * 128;
    const int E = 128 * 128;
    const int F = 384 * 128;
    const int G = 128 * 128;
    if (i < A) { int k = i / 128, c = i % 128; g_WopT[i] = wop[c * FIN + k]; return; }
    i -= A;
    if (i < B) {
        int it = i / (128 * 256); int r = i % (128 * 256);
        int k = r / 256, c2 = r % 256;
        float v = (c2 < 128) ? ew[(it * 128 + c2) * 260 + k]
                             : ew[(it * 128 + (c2 - 128)) * 260 + 128 + k];
        (it ? g_WpT1 : g_WpT0)[k * 256 + c2] = v; return;
    }
    i -= B;
    if (i < C) {
        int it = i / (128 * 4); int r = i % (128 * 4);
        (it ? g_WeP1 : g_WeP0)[r] = ew[(it * 128 + r / 4) * 260 + 256 + (r & 3)]; return;
    }
    i -= C;
    if (i < D) { int k = i / 128, c = i % 128; g_WskipT[i] = wskip[c * 128 + k]; return; }
    i -= D;
    if (i < E) { int k = i / 128, c = i % 128; g_WgeoT[i]  = wgeo[c * 128 + k]; return; }
    i -= E;
    if (i < F) { int j = i / 128, c = i % 128; g_W2T[i] = w2[c * 384 + j]; return; }
    i -= F;
    if (i < G) { int j = i / 128, c = i % 128; g_WgT[i] = wg2[c * 128 + j]; return; }
}

// ---------------- CSR build ----------------
__global__ void k_hist(const int* __restrict__ eidx) {
    int e = blockIdx.x * 256 + threadIdx.x;
    if (e < N_EDGES) atomicAdd(&g_deg[eidx[2 * e]], 1);
}

__global__ void k_scan() {
    __shared__ int part[1024];
    const int CH = 20;                // 1024*20 >= 20000
    int t = threadIdx.x;
    int base = t * CH;
    int local[CH];
    int s = 0;
#pragma unroll
    for (int k = 0; k < CH; k++) {
        int idx = base + k;
        int d = (idx < N_NODES) ? g_deg[idx] : 0;
        local[k] = d; s += d;
    }
    part[t] = s;
    __syncthreads();
    for (int off = 1; off < 1024; off <<= 1) {
        int v = (t >= off) ? part[t - off] : 0;
        __syncthreads();
        part[t] += v;
        __syncthreads();
    }
    int run = part[t] - s;            // exclusive prefix
#pragma unroll
    for (int k = 0; k < CH; k++) {
        int idx = base + k;
        if (idx < N_NODES) { g_off[idx] = run; g_pos[idx] = run; run += local[k]; }
    }
}

__global__ void k_sort(const int* __restrict__ eidx, const float* __restrict__ etype) {
    int e = blockIdx.x * 256 + threadIdx.x;
    if (e < N_EDGES) {
        int f = eidx[2 * e], to = eidx[2 * e + 1];
        int slot = atomicAdd(&g_pos[f], 1);
        g_toS[slot] = to;
        g_efS[slot] = *(const float4*)(etype + 4 * e);
    }
}

// ---------------- generic fp32 GEMM (nodes x K) @ (K x COUT) ----------------
enum { XS_EXT = 0, XS_CF0 = 1, XS_CF1 = 2 };
enum { WS_OP = 0, WS_P0 = 1, WS_P1 = 2, WS_SKIP = 3, WS_GEO = 4 };
enum { YS_CF0 = 0, YS_P = 1 };

__device__ __forceinline__ const float* sel_x(int s, const float* ext) {
    if (s == XS_CF0) return g_cf0;
    if (s == XS_CF1) return g_cf1;
    return ext;
}
__device__ __forceinline__ const float* sel_w(int s) {
    switch (s) {
        case WS_OP:   return g_WopT;
        case WS_P0:   return g_WpT0;
        case WS_P1:   return g_WpT1;
        case WS_SKIP: return g_WskipT;
        default:      return g_WgeoT;
    }
}
__device__ __forceinline__ float* sel_y(int s) { return (s == YS_CF0) ? g_cf0 : g_P; }

template<int K, int COUT, bool STORE, bool HASBIAS, bool EXISTS, bool COLMAX>
__global__ void __launch_bounds__(256)
k_gemm(const float* __restrict__ Xext, int xsel, int wsel,
       const float* __restrict__ bias, const float* __restrict__ exists,
       int ysel, int slot) {
    constexpr int CH_T = COUT / 8;       // threads along channel dim
    constexpr int ND_T = 256 / CH_T;     // threads along node dim
    constexpr int TN   = ND_T * 4;       // nodes per block
    constexpr int TNP  = TN + 4;         // padded pitch (16B-aligned, conflict-reducing)
    constexpr int NKC  = (K + 31) / 32;

    __shared__ __align__(16) float sW[32 * COUT];
    __shared__ __align__(16) float sX[32 * TNP];
    __shared__ __align__(16) float sRed[COLMAX ? ND_T * COUT : 4];

    const float* X  = sel_x(xsel, Xext);
    const float* Wt = sel_w(wsel);

    int tid = threadIdx.x;
    int ct = tid % CH_T, nt = tid / CH_T;
    int nb = blockIdx.x * TN;

    float acc[8][4];
#pragma unroll
    for (int c = 0; c < 8; c++)
#pragma unroll
        for (int n = 0; n < 4; n++) acc[c][n] = 0.f;

    for (int kc = 0; kc < NKC; kc++) {
        int k0 = kc * 32;
#pragma unroll
        for (int p = 0; p < COUT * 32 / 256; p++) {
            int idx = tid + p * 256;
            int c = idx % COUT, kk = idx / COUT;
            int k = k0 + kk;
            sW[kk * COUT + c] = (k < K) ? Wt[k * COUT + c] : 0.f;
        }
#pragma unroll
        for (int p = 0; p < TN * 32 / 256; p++) {
            int idx = tid + p * 256;
            int kk = idx & 31, n = idx >> 5;
            int node = nb + n, k = k0 + kk;
            sX[kk * TNP + n] = (node < N_NODES && k < K) ? X[node * K + k] : 0.f;
        }
        __syncthreads();
#pragma unroll
        for (int kk = 0; kk < 32; kk++) {
            float4 xv = *(const float4*)(sX + kk * TNP + nt * 4);
            float4 w0 = *(const float4*)(sW + kk * COUT + ct * 8);
            float4 w1 = *(const float4*)(sW + kk * COUT + ct * 8 + 4);
            float xr[4] = { xv.x, xv.y, xv.z, xv.w };
            float wr[8] = { w0.x, w0.y, w0.z, w0.w, w1.x, w1.y, w1.z, w1.w };
#pragma unroll
            for (int c = 0; c < 8; c++)
#pragma unroll
                for (int n = 0; n < 4; n++)
                    acc[c][n] = fmaf(wr[c], xr[n], acc[c][n]);
        }
        __syncthreads();
    }

    // epilogue
    float b[8];
#pragma unroll
    for (int c = 0; c < 8; c++) b[c] = HASBIAS ? bias[ct * 8 + c] : 0.f;
    float lmax[8];
#pragma unroll
    for (int c = 0; c < 8; c++) lmax[c] = -3.402823466e38f;

    float* Y = STORE ? sel_y(ysel) : nullptr;
#pragma unroll
    for (int n = 0; n < 4; n++) {
        int node = nb + nt * 4 + n;
        if (node < N_NODES) {
            float ex = EXISTS ? exists[node] : 1.f;
            float y[8];
#pragma unroll
            for (int c = 0; c < 8; c++) {
                float v = acc[c][n] + b[c];
                if (EXISTS) v *= ex;
                y[c] = v;
                if (COLMAX) lmax[c] = fmaxf(lmax[c], v);
            }
            if (STORE) {
                float4 y0 = { y[0], y[1], y[2], y[3] };
                float4 y1 = { y[4], y[5], y[6], y[7] };
                *(float4*)(Y + node * COUT + ct * 8)     = y0;
                *(float4*)(Y + node * COUT + ct * 8 + 4) = y1;
            }
        }
    }

    if (COLMAX) {
#pragma unroll
        for (int c = 0; c < 8; c++) sRed[nt * COUT + ct * 8 + c] = lmax[c];
        __syncthreads();
        for (int c = tid; c < COUT; c += 256) {
            float m = sRed[c];
#pragma unroll
            for (int r = 1; r < ND_T; r++) m = fmaxf(m, sRed[r * COUT + c]);
            atomicMax(&g_keys[slot * 128 + c], fkey(m));
        }
    }
}

// ---------------- per-node gather + max (replaces scatter-max) ----------------
template<bool STORE>
__global__ void __launch_bounds__(512)
k_edge(const float* __restrict__ eb, int wesel, int slot) {
    const float* WeP = wesel ? g_WeP1 : g_WeP0;
    int warp = threadIdx.x >> 5, lane = threadIdx.x & 31;
    int v = blockIdx.x * 16 + warp;
    __shared__ __align__(16) float sRed[16 * 128];

    float4 acc = make_float4(0.f, 0.f, 0.f, 0.f);   // scatter-init-zero semantics
    if (v < N_NODES) {
        const float4* P4 = (const float4*)g_P;
        float4 pa = P4[v * 64 + lane];
        float4 b4 = *(const float4*)(eb + lane * 4);
        float4 base = { pa.x + b4.x, pa.y + b4.y, pa.z + b4.z, pa.w + b4.w };
        const float4* We4 = (const float4*)WeP;
        float4 we0 = We4[lane * 4 + 0];
        float4 we1 = We4[lane * 4 + 1];
        float4 we2 = We4[lane * 4 + 2];
        float4 we3 = We4[lane * 4 + 3];
        int start = g_off[v], deg = g_deg[v];
#pragma unroll 2
        for (int j = 0; j < deg; j++) {
            int to = g_toS[start + j];
            float4 ef = g_efS[start + j];
            float4 pb = P4[to * 64 + 32 + lane];
            float d0 = fmaf(we0.x, ef.x, fmaf(we0.y, ef.y, fmaf(we0.z, ef.z, we0.w * ef.w)));
            float d1 = fmaf(we1.x, ef.x, fmaf(we1.y, ef.y, fmaf(we1.z, ef.z, we1.w * ef.w)));
            float d2 = fmaf(we2.x, ef.x, fmaf(we2.y, ef.y, fmaf(we2.z, ef.z, we2.w * ef.w)));
            float d3 = fmaf(we3.x, ef.x, fmaf(we3.y, ef.y, fmaf(we3.z, ef.z, we3.w * ef.w)));
            float v0 = base.x + pb.x + d0;
            float v1 = base.y + pb.y + d1;
            float v2 = base.z + pb.z + d2;
            float v3 = base.w + pb.w + d3;
            acc.x = fmaxf(acc.x, fmaxf(v0, 0.01f * v0));
            acc.y = fmaxf(acc.y, fmaxf(v1, 0.01f * v1));
            acc.z = fmaxf(acc.z, fmaxf(v2, 0.01f * v2));
            acc.w = fmaxf(acc.w, fmaxf(v3, 0.01f * v3));
        }
        if (STORE) *(float4*)(g_cf1 + v * 128 + lane * 4) = acc;
    }
    *(float4*)(sRed + warp * 128 + lane * 4) = acc;
    __syncthreads();
    int t = threadIdx.x;
    if (t < 128) {
        float m = sRed[t];
#pragma unroll
        for (int r = 1; r < 16; r++) m = fmaxf(m, sRed[r * 128 + t]);
        atomicMax(&g_keys[slot * 128 + t], fkey(m));
    }
}

// ---------------- finalize: tiny GEMMs + group norm ----------------
__global__ void __launch_bounds__(384)
k_final(const float* __restrict__ second_b, const float* __restrict__ sgeo_b,
        const float* __restrict__ gnw, const float* __restrict__ gnb,
        float* __restrict__ out) {
    __shared__ float spf[384];
    __shared__ float spg[128];
    int t = threadIdx.x;
    if (t < 384) spf[t] = fdec(g_keys[t]);              // slots 0..2 concatenated
    if (t < 128) spg[t] = leaky(fdec(g_keys[512 + t])); // pg = leaky(max cg), slot 4
    __syncthreads();
    if (t < 128) {
        float a = 0.f;
#pragma unroll 4
        for (int j = 0; j < 384; j++) a = fmaf(spf[j], g_W2T[j * 128 + t], a);
        a += second_b[t];
        out[t] = leaky(a);

        float g = 0.f;
#pragma unroll 4
        for (int j = 0; j < 128; j++) g = fmaf(spg[j], g_WgT[j * 128 + t], g);
        g += sgeo_b[t];

        // group norm: 16 groups of 8 contiguous channels -> shfl within 8-lane segments
        float s = g;
        s += __shfl_xor_sync(0xffffffffu, s, 1, 8);
        s += __shfl_xor_sync(0xffffffffu, s, 2, 8);
        s += __shfl_xor_sync(0xffffffffu, s, 4, 8);
        float mu = s * 0.125f;
        float d = g - mu;
        float q = d * d;
        q += __shfl_xor_sync(0xffffffffu, q, 1, 8);
        q += __shfl_xor_sync(0xffffffffu, q, 2, 8);
        q += __shfl_xor_sync(0xffffffffu, q, 4, 8);
        float var = q * 0.125f;
        float xn = d * rsqrtf(var + 1e-5f);
        float y = xn * gnw[t] + gnb[t];
        float sgv = fdec(g_keys[384 + t]);              // slot 3 = skip max
        float o = leaky(sgv) + y;
        out[128 + t] = leaky(o);
    }
}

// ---------------- host launcher ----------------
extern "C" void kernel_launch(void* const* d_in, const int* in_sizes, int n_in,
                              void* d_out, int out_size) {
    const float* child_feats = (const float*)d_in[0];
    const float* child_geo   = (const float*)d_in[1];
    const float* exists      = (const float*)d_in[2];
    const float* etype       = (const float*)d_in[3];
    const int*   eidx        = (const int*)d_in[4];
    const float* wop   = (const float*)d_in[5];
    const float* bop   = (const float*)d_in[6];
    const float* w2    = (const float*)d_in[7];
    const float* b2    = (const float*)d_in[8];
    const float* ew    = (const float*)d_in[9];
    const float* ebias = (const float*)d_in[10];
    const float* wgeo  = (const float*)d_in[11];
    const float* bgeo  = (const float*)d_in[12];
    const float* wg2   = (const float*)d_in[13];
    const float* bg2   = (const float*)d_in[14];
    const float* gnw   = (const float*)d_in[15];
    const float* gnb   = (const float*)d_in[16];
    const float* wskip = (const float*)d_in[17];
    const float* bskip = (const float*)d_in[18];
    float* out = (float*)d_out;

    (void)in_sizes; (void)n_in; (void)out_size;

    // init + weight packing + CSR build
    k_init<<<(N_NODES + 255) / 256, 256>>>();
    {
        const int total = FIN * 128 + 2 * 128 * 256 + 2 * 128 * 4
                        + 128 * 128 + 128 * 128 + 384 * 128 + 128 * 128;
        k_prep<<<(total + 255) / 256, 256>>>(wop, ew, wskip, wgeo, w2, wg2);
    }
    k_hist<<<(N_EDGES + 255) / 256, 256>>>(eidx);
    k_scan<<<1, 1024>>>();
    k_sort<<<(N_EDGES + 255) / 256, 256>>>(eidx, etype);

    // cf0 = (child_feats @ Wop^T + b) * exists ; col-max -> slot 0
    k_gemm<FIN, 128, true, true, true, true><<<(N_NODES + 63) / 64, 256>>>(
        child_feats, XS_EXT, WS_OP, bop, exists, YS_CF0, 0);

    // iteration 0
    k_gemm<128, 256, true, false, false, false><<<N_NODES / 32, 256>>>(
        nullptr, XS_CF0, WS_P0, nullptr, nullptr, YS_P, 0);
    k_edge<true><<<N_NODES / 16, 512>>>(ebias, 0, 1);

    // iteration 1
    k_gemm<128, 256, true, false, false, false><<<N_NODES / 32, 256>>>(
        nullptr, XS_CF1, WS_P1, nullptr, nullptr, YS_P, 0);
    k_edge<false><<<N_NODES / 16, 512>>>(ebias + 128, 1, 2);

    // geo path: only column maxes needed
    k_gemm<128, 128, false, true, true, true><<<(N_NODES + 63) / 64, 256>>>(
        child_geo, XS_EXT, WS_SKIP, bskip, exists, YS_CF0, 3);
    k_gemm<128, 128, false, true, true, true><<<(N_NODES + 63) / 64, 256>>>(
        child_geo, XS_EXT, WS_GEO, bgeo, exists, YS_CF0, 4);

    // finalize
    k_final<<<1, 384>>>(b2, bg2, gnw, gnb, out);
}

// round 3
// speedup vs baseline: 1.0040x; 1.0040x over previous
#include <cuda_runtime.h>
#include <math.h>

#define N_NODES 20000
#define N_EDGES 320000
#define HDIM 128
#define FIN 162

// ---------------- device scratch (static, no allocation) ----------------
__device__ float g_cf0[N_NODES * HDIM];
__device__ float g_cf1[N_NODES * HDIM];
__device__ float g_P[N_NODES * 2 * HDIM];

__device__ int   g_deg[N_NODES];
__device__ int   g_off[N_NODES];
__device__ int   g_pos[N_NODES];
__device__ int   g_toS[N_EDGES];
__device__ float4 g_efS[N_EDGES];

// col-max key slots: 0,1,2 = parent feats per iter; 3 = skip max; 4 = cg max
__device__ unsigned g_keys[5 * 128];

// packed / transposed weights
__device__ float g_WopT[FIN * 128];      // [k][c]
__device__ float g_WpT0[128 * 256];      // [k][c2]  (Wa|Wb iter0)
__device__ float g_WpT1[128 * 256];
__device__ float g_WeP0[128 * 4];        // [c][t]
__device__ float g_WeP1[128 * 4];
__device__ float g_WskipT[128 * 128];
__device__ float g_WgeoT[128 * 128];
__device__ float g_W2T[384 * 128];       // second_w transposed [j][c]
__device__ float g_WgT[128 * 128];       // second_geo_w transposed [j][c]

// ---------------- helpers ----------------
__device__ __forceinline__ unsigned fkey(float f) {
    unsigned u = __float_as_uint(f);
    return (u & 0x80000000u) ? ~u : (u | 0x80000000u);
}
__device__ __forceinline__ float fdec(unsigned k) {
    unsigned u = (k & 0x80000000u) ? (k & 0x7fffffffu) : ~k;
    return __uint_as_float(u);
}
__device__ __forceinline__ float leaky(float x) { return fmaxf(x, 0.01f * x); }

// ---------------- init ----------------
__global__ void k_init() {
    int i = blockIdx.x * 256 + threadIdx.x;
    if (i < N_NODES) g_deg[i] = 0;
    if (i < 5 * 128) g_keys[i] = fkey(-3.402823466e38f);
}

// ---------------- weight pack / transpose ----------------
__global__ void k_prep(const float* __restrict__ wop, const float* __restrict__ ew,
                       const float* __restrict__ wskip, const float* __restrict__ wgeo,
                       const float* __restrict__ w2, const float* __restrict__ wg2) {
    int i = blockIdx.x * 256 + threadIdx.x;
    const int A = FIN * 128;
    const int B = 2 * 128 * 256;
    const int C = 2 * 128 * 4;
    const int D = 128 * 128;
    const int E = 128 * 128;
    const int F = 384 * 128;
    const int G = 128 * 128;
    if (i < A) { int k = i / 128, c = i % 128; g_WopT[i] = wop[c * FIN + k]; return; }
    i -= A;
    if (i < B) {
        int it = i / (128 * 256); int r = i % (128 * 256);
        int k = r / 256, c2 = r % 256;
        float v = (c2 < 128) ? ew[(it * 128 + c2) * 260 + k]
                             : ew[(it * 128 + (c2 - 128)) * 260 + 128 + k];
        (it ? g_WpT1 : g_WpT0)[k * 256 + c2] = v; return;
    }
    i -= B;
    if (i < C) {
        int it = i / (128 * 4); int r = i % (128 * 4);
        (it ? g_WeP1 : g_WeP0)[r] = ew[(it * 128 + r / 4) * 260 + 256 + (r & 3)]; return;
    }
    i -= C;
    if (i < D) { int k = i / 128, c = i % 128; g_WskipT[i] = wskip[c * 128 + k]; return; }
    i -= D;
    if (i < E) { int k = i / 128, c = i % 128; g_WgeoT[i]  = wgeo[c * 128 + k]; return; }
    i -= E;
    if (i < F) { int j = i / 128, c = i % 128; g_W2T[i] = w2[c * 384 + j]; return; }
    i -= F;
    if (i < G) { int j = i / 128, c = i % 128; g_WgT[i] = wg2[c * 128 + j]; return; }
}

// ---------------- CSR build ----------------
__global__ void k_hist(const int* __restrict__ eidx) {
    int e = blockIdx.x * 256 + threadIdx.x;
    if (e < N_EDGES) atomicAdd(&g_deg[eidx[2 * e]], 1);
}

__global__ void k_scan() {
    __shared__ int part[1024];
    const int CH = 20;                // 1024*20 >= 20000
    int t = threadIdx.x;
    int base = t * CH;
    int local[CH];
    int s = 0;
#pragma unroll
    for (int k = 0; k < CH; k++) {
        int idx = base + k;
        int d = (idx < N_NODES) ? g_deg[idx] : 0;
        local[k] = d; s += d;
    }
    part[t] = s;
    __syncthreads();
    for (int off = 1; off < 1024; off <<= 1) {
        int v = (t >= off) ? part[t - off] : 0;
        __syncthreads();
        part[t] += v;
        __syncthreads();
    }
    int run = part[t] - s;            // exclusive prefix
#pragma unroll
    for (int k = 0; k < CH; k++) {
        int idx = base + k;
        if (idx < N_NODES) { g_off[idx] = run; g_pos[idx] = run; run += local[k]; }
    }
}

__global__ void k_sort(const int* __restrict__ eidx, const float* __restrict__ etype) {
    int e = blockIdx.x * 256 + threadIdx.x;
    if (e < N_EDGES) {
        int f = eidx[2 * e], to = eidx[2 * e + 1];
        int slot = atomicAdd(&g_pos[f], 1);
        g_toS[slot] = to;
        g_efS[slot] = *(const float4*)(etype + 4 * e);
    }
}

// ---------------- generic fp32 GEMM (nodes x K) @ (K x COUT) ----------------
enum { XS_EXT = 0, XS_CF0 = 1, XS_CF1 = 2 };
enum { WS_OP = 0, WS_P0 = 1, WS_P1 = 2, WS_SKIP = 3, WS_GEO = 4 };
enum { YS_CF0 = 0, YS_P = 1 };

__device__ __forceinline__ const float* sel_x(int s, const float* ext) {
    if (s == XS_CF0) return g_cf0;
    if (s == XS_CF1) return g_cf1;
    return ext;
}
__device__ __forceinline__ const float* sel_w(int s) {
    switch (s) {
        case WS_OP:   return g_WopT;
        case WS_P0:   return g_WpT0;
        case WS_P1:   return g_WpT1;
        case WS_SKIP: return g_WskipT;
        default:      return g_WgeoT;
    }
}
__device__ __forceinline__ float* sel_y(int s) { return (s == YS_CF0) ? g_cf0 : g_P; }

template<int K, int COUT, bool STORE, bool HASBIAS, bool EXISTS, bool COLMAX>
__global__ void __launch_bounds__(256)
k_gemm(const float* __restrict__ Xext, int xsel, int wsel,
       const float* __restrict__ bias, const float* __restrict__ exists,
       int ysel, int slot) {
    constexpr int CH_T = COUT / 8;       // threads along channel dim
    constexpr int ND_T = 256 / CH_T;     // threads along node dim
    constexpr int TN   = ND_T * 4;       // nodes per block
    constexpr int TNP  = TN + 4;         // padded pitch (16B-aligned, conflict-reducing)
    constexpr int NKC  = (K + 31) / 32;

    __shared__ __align__(16) float sW[32 * COUT];
    __shared__ __align__(16) float sX[32 * TNP];
    __shared__ __align__(16) float sRed[COLMAX ? ND_T * COUT : 4];

    const float* X  = sel_x(xsel, Xext);
    const float* Wt = sel_w(wsel);

    int tid = threadIdx.x;
    int ct = tid % CH_T, nt = tid / CH_T;
    int nb = blockIdx.x * TN;

    float acc[8][4];
#pragma unroll
    for (int c = 0; c < 8; c++)
#pragma unroll
        for (int n = 0; n < 4; n++) acc[c][n] = 0.f;

    for (int kc = 0; kc < NKC; kc++) {
        int k0 = kc * 32;
#pragma unroll
        for (int p = 0; p < COUT * 32 / 256; p++) {
            int idx = tid + p * 256;
            int c = idx % COUT, kk = idx / COUT;
            int k = k0 + kk;
            sW[kk * COUT + c] = (k < K) ? Wt[k * COUT + c] : 0.f;
        }
#pragma unroll
        for (int p = 0; p < TN * 32 / 256; p++) {
            int idx = tid + p * 256;
            int kk = idx & 31, n = idx >> 5;
            int node = nb + n, k = k0 + kk;
            sX[kk * TNP + n] = (node < N_NODES && k < K) ? X[node * K + k] : 0.f;
        }
        __syncthreads();
#pragma unroll
        for (int kk = 0; kk < 32; kk++) {
            float4 xv = *(const float4*)(sX + kk * TNP + nt * 4);
            float4 w0 = *(const float4*)(sW + kk * COUT + ct * 8);
            float4 w1 = *(const float4*)(sW + kk * COUT + ct * 8 + 4);
            float xr[4] = { xv.x, xv.y, xv.z, xv.w };
            float wr[8] = { w0.x, w0.y, w0.z, w0.w, w1.x, w1.y, w1.z, w1.w };
#pragma unroll
            for (int c = 0; c < 8; c++)
#pragma unroll
                for (int n = 0; n < 4; n++)
                    acc[c][n] = fmaf(wr[c], xr[n], acc[c][n]);
        }
        __syncthreads();
    }

    // epilogue
    float b[8];
#pragma unroll
    for (int c = 0; c < 8; c++) b[c] = HASBIAS ? bias[ct * 8 + c] : 0.f;
    float lmax[8];
#pragma unroll
    for (int c = 0; c < 8; c++) lmax[c] = -3.402823466e38f;

    float* Y = STORE ? sel_y(ysel) : nullptr;
#pragma unroll
    for (int n = 0; n < 4; n++) {
        int node = nb + nt * 4 + n;
        if (node < N_NODES) {
            float ex = EXISTS ? exists[node] : 1.f;
            float y[8];
#pragma unroll
            for (int c = 0; c < 8; c++) {
                float v = acc[c][n] + b[c];
                if (EXISTS) v *= ex;
                y[c] = v;
                if (COLMAX) lmax[c] = fmaxf(lmax[c], v);
            }
            if (STORE) {
                float4 y0 = { y[0], y[1], y[2], y[3] };
                float4 y1 = { y[4], y[5], y[6], y[7] };
                *(float4*)(Y + node * COUT + ct * 8)     = y0;
                *(float4*)(Y + node * COUT + ct * 8 + 4) = y1;
            }
        }
    }

    if (COLMAX) {
#pragma unroll
        for (int c = 0; c < 8; c++) sRed[nt * COUT + ct * 8 + c] = lmax[c];
        __syncthreads();
        for (int c = tid; c < COUT; c += 256) {
            float m = sRed[c];
#pragma unroll
            for (int r = 1; r < ND_T; r++) m = fmaxf(m, sRed[r * COUT + c]);
            atomicMax(&g_keys[slot * 128 + c], fkey(m));
        }
    }
}

// ---------------- per-node gather + max (replaces scatter-max) ----------------
template<bool STORE>
__global__ void __launch_bounds__(512)
k_edge(const float* __restrict__ eb, int wesel, int slot) {
    const float* WeP = wesel ? g_WeP1 : g_WeP0;
    int warp = threadIdx.x >> 5, lane = threadIdx.x & 31;
    int v = blockIdx.x * 16 + warp;
    __shared__ __align__(16) float sRed[16 * 128];

    float4 acc = make_float4(0.f, 0.f, 0.f, 0.f);   // scatter-init-zero semantics
    if (v < N_NODES) {
        const float4* P4 = (const float4*)g_P;
        float4 pa = P4[v * 64 + lane];
        float4 b4 = *(const float4*)(eb + lane * 4);
        float4 base = { pa.x + b4.x, pa.y + b4.y, pa.z + b4.z, pa.w + b4.w };
        const float4* We4 = (const float4*)WeP;
        float4 we0 = We4[lane * 4 + 0];
        float4 we1 = We4[lane * 4 + 1];
        float4 we2 = We4[lane * 4 + 2];
        float4 we3 = We4[lane * 4 + 3];
        int start = g_off[v], deg = g_deg[v];
#pragma unroll 2
        for (int j = 0; j < deg; j++) {
            int to = g_toS[start + j];
            float4 ef = g_efS[start + j];
            float4 pb = P4[to * 64 + 32 + lane];
            float d0 = fmaf(we0.x, ef.x, fmaf(we0.y, ef.y, fmaf(we0.z, ef.z, we0.w * ef.w)));
            float d1 = fmaf(we1.x, ef.x, fmaf(we1.y, ef.y, fmaf(we1.z, ef.z, we1.w * ef.w)));
            float d2 = fmaf(we2.x, ef.x, fmaf(we2.y, ef.y, fmaf(we2.z, ef.z, we2.w * ef.w)));
            float d3 = fmaf(we3.x, ef.x, fmaf(we3.y, ef.y, fmaf(we3.z, ef.z, we3.w * ef.w)));
            float v0 = base.x + pb.x + d0;
            float v1 = base.y + pb.y + d1;
            float v2 = base.z + pb.z + d2;
            float v3 = base.w + pb.w + d3;
            acc.x = fmaxf(acc.x, fmaxf(v0, 0.01f * v0));
            acc.y = fmaxf(acc.y, fmaxf(v1, 0.01f * v1));
            acc.z = fmaxf(acc.z, fmaxf(v2, 0.01f * v2));
            acc.w = fmaxf(acc.w, fmaxf(v3, 0.01f * v3));
        }
        if (STORE) *(float4*)(g_cf1 + v * 128 + lane * 4) = acc;
    }
    *(float4*)(sRed + warp * 128 + lane * 4) = acc;
    __syncthreads();
    int t = threadIdx.x;
    if (t < 128) {
        float m = sRed[t];
#pragma unroll
        for (int r = 1; r < 16; r++) m = fmaxf(m, sRed[r * 128 + t]);
        atomicMax(&g_keys[slot * 128 + t], fkey(m));
    }
}

// ---------------- finalize: tiny GEMMs + group norm ----------------
__global__ void __launch_bounds__(384)
k_final(const float* __restrict__ second_b, const float* __restrict__ sgeo_b,
        const float* __restrict__ gnw, const float* __restrict__ gnb,
        float* __restrict__ out) {
    __shared__ float spf[384];
    __shared__ float spg[128];
    int t = threadIdx.x;
    if (t < 384) spf[t] = fdec(g_keys[t]);              // slots 0..2 concatenated
    if (t < 128) spg[t] = leaky(fdec(g_keys[512 + t])); // pg = leaky(max cg), slot 4
    __syncthreads();
    if (t < 128) {
        float a = 0.f;
#pragma unroll 4
        for (int j = 0; j < 384; j++) a = fmaf(spf[j], g_W2T[j * 128 + t], a);
        a += second_b[t];
        out[t] = leaky(a);

        float g = 0.f;
#pragma unroll 4
        for (int j = 0; j < 128; j++) g = fmaf(spg[j], g_WgT[j * 128 + t], g);
        g += sgeo_b[t];

        // group norm: 16 groups of 8 contiguous channels -> shfl within 8-lane segments
        float s = g;
        s += __shfl_xor_sync(0xffffffffu, s, 1, 8);
        s += __shfl_xor_sync(0xffffffffu, s, 2, 8);
        s += __shfl_xor_sync(0xffffffffu, s, 4, 8);
        float mu = s * 0.125f;
        float d = g - mu;
        float q = d * d;
        q += __shfl_xor_sync(0xffffffffu, q, 1, 8);
        q += __shfl_xor_sync(0xffffffffu, q, 2, 8);
        q += __shfl_xor_sync(0xffffffffu, q, 4, 8);
        float var = q * 0.125f;
        float xn = d * rsqrtf(var + 1e-5f);
        float y = xn * gnw[t] + gnb[t];
        float sgv = fdec(g_keys[384 + t]);              // slot 3 = skip max
        float o = leaky(sgv) + y;
        out[128 + t] = leaky(o);
    }
}

// ---------------- host launcher ----------------
extern "C" void kernel_launch(void* const* d_in, const int* in_sizes, int n_in,
                              void* d_out, int out_size) {
    const float* child_feats = (const float*)d_in[0];
    const float* child_geo   = (const float*)d_in[1];
    const float* exists      = (const float*)d_in[2];
    const float* etype       = (const float*)d_in[3];
    const int*   eidx        = (const int*)d_in[4];
    const float* wop   = (const float*)d_in[5];
    const float* bop   = (const float*)d_in[6];
    const float* w2    = (const float*)d_in[7];
    const float* b2    = (const float*)d_in[8];
    const float* ew    = (const float*)d_in[9];
    const float* ebias = (const float*)d_in[10];
    const float* wgeo  = (const float*)d_in[11];
    const float* bgeo  = (const float*)d_in[12];
    const float* wg2   = (const float*)d_in[13];
    const float* bg2   = (const float*)d_in[14];
    const float* gnw   = (const float*)d_in[15];
    const float* gnb   = (const float*)d_in[16];
    const float* wskip = (const float*)d_in[17];
    const float* bskip = (const float*)d_in[18];
    float* out = (float*)d_out;

    (void)in_sizes; (void)n_in; (void)out_size;

    // init + weight packing + CSR build
    k_init<<<(N_NODES + 255) / 256, 256>>>();
    {
        const int total = FIN * 128 + 2 * 128 * 256 + 2 * 128 * 4
                        + 128 * 128 + 128 * 128 + 384 * 128 + 128 * 128;
        k_prep<<<(total + 255) / 256, 256>>>(wop, ew, wskip, wgeo, w2, wg2);
    }
    k_hist<<<(N_EDGES + 255) / 256, 256>>>(eidx);
    k_scan<<<1, 1024>>>();
    k_sort<<<(N_EDGES + 255) / 256, 256>>>(eidx, etype);

    // cf0 = (child_feats @ Wop^T + b) * exists ; col-max -> slot 0
    k_gemm<FIN, 128, true, true, true, true><<<(N_NODES + 63) / 64, 256>>>(
        child_feats, XS_EXT, WS_OP, bop, exists, YS_CF0, 0);

    // iteration 0
    k_gemm<128, 256, true, false, false, false><<<N_NODES / 32, 256>>>(
        nullptr, XS_CF0, WS_P0, nullptr, nullptr, YS_P, 0);
    k_edge<true><<<N_NODES / 16, 512>>>(ebias, 0, 1);

    // iteration 1
    k_gemm<128, 256, true, false, false, false><<<N_NODES / 32, 256>>>(
        nullptr, XS_CF1, WS_P1, nullptr, nullptr, YS_P, 0);
    k_edge<false><<<N_NODES / 16, 512>>>(ebias + 128, 1, 2);

    // geo path: only column maxes needed
    k_gemm<128, 128, false, true, true, true><<<(N_NODES + 63) / 64, 256>>>(
        child_geo, XS_EXT, WS_SKIP, bskip, exists, YS_CF0, 3);
    k_gemm<128, 128, false, true, true, true><<<(N_NODES + 63) / 64, 256>>>(
        child_geo, XS_EXT, WS_GEO, bgeo, exists, YS_CF0, 4);

    // finalize
    k_final<<<1, 384>>>(b2, bg2, gnw, gnb, out);
}

// round 6
// speedup vs baseline: 1.1091x; 1.1047x over previous
#include <cuda_runtime.h>
#include <math.h>

#define N_NODES 20000
#define N_EDGES 320000
#define HDIM 128
#define FIN 162

typedef unsigned long long u64;

// ---------------- device scratch (static, no allocation) ----------------
__device__ float g_cf0[N_NODES * HDIM];
__device__ float g_cf1[N_NODES * HDIM];
__device__ float g_P[N_NODES * 2 * HDIM];

__device__ int   g_deg[N_NODES];
__device__ int   g_off[N_NODES];
__device__ int   g_pos[N_NODES];
__device__ int   g_ctr;
__device__ int   g_toS[N_EDGES];
__device__ float4 g_efS[N_EDGES];

// col-max key slots: 0,1,2 = parent feats per iter; 3 = skip max; 4 = cg max
__device__ unsigned g_keys[5 * 128];

// packed / transposed weights
__device__ float g_WopT[FIN * 128];      // [k][c]
__device__ float g_WpT0[128 * 256];      // [k][c2]  (Wa|Wb iter0)
__device__ float g_WpT1[128 * 256];
__device__ float g_WeP0[128 * 4];        // [c][t]
__device__ float g_WeP1[128 * 4];
__device__ float g_WskipT[128 * 128];
__device__ float g_WgeoT[128 * 128];
__device__ float g_W2T[384 * 128];       // second_w transposed [j][c]
__device__ float g_WgT[128 * 128];       // second_geo_w transposed [j][c]

// ---------------- helpers ----------------
__device__ __forceinline__ unsigned fkey(float f) {
    unsigned u = __float_as_uint(f);
    return (u & 0x80000000u) ? ~u : (u | 0x80000000u);
}
__device__ __forceinline__ float fdec(unsigned k) {
    unsigned u = (k & 0x80000000u) ? (k & 0x7fffffffu) : ~k;
    return __uint_as_float(u);
}
__device__ __forceinline__ float leaky(float x) { return fmaxf(x, 0.01f * x); }

__device__ __forceinline__ u64 pack2(float lo, float hi) {
    u64 r; asm("mov.b64 %0, {%1, %2};" : "=l"(r) : "f"(lo), "f"(hi)); return r;
}
__device__ __forceinline__ void unpack2(u64 v, float& lo, float& hi) {
    asm("mov.b64 {%0, %1}, %2;" : "=f"(lo), "=f"(hi) : "l"(v));
}
__device__ __forceinline__ u64 fma2(u64 a, u64 b, u64 c) {
    u64 d; asm("fma.rn.f32x2 %0, %1, %2, %3;" : "=l"(d) : "l"(a), "l"(b), "l"(c)); return d;
}

// ---------------- init ----------------
__global__ void k_init() {
    int i = blockIdx.x * 256 + threadIdx.x;
    if (i < N_NODES) g_deg[i] = 0;
    if (i < 5 * 128) g_keys[i] = fkey(-3.402823466e38f);
    if (i == 0) g_ctr = 0;
}

// ---------------- weight pack / transpose ----------------
__global__ void k_prep(const float* __restrict__ wop, const float* __restrict__ ew,
                       const float* __restrict__ wskip, const float* __restrict__ wgeo,
                       const float* __restrict__ w2, const float* __restrict__ wg2) {
    int i = blockIdx.x * 256 + threadIdx.x;
    const int A = FIN * 128;
    const int B = 2 * 128 * 256;
    const int C = 2 * 128 * 4;
    const int D = 128 * 128;
    const int E = 128 * 128;
    const int F = 384 * 128;
    const int G = 128 * 128;
    if (i < A) { int k = i / 128, c = i % 128; g_WopT[i] = wop[c * FIN + k]; return; }
    i -= A;
    if (i < B) {
        int it = i / (128 * 256); int r = i % (128 * 256);
        int k = r / 256, c2 = r % 256;
        float v = (c2 < 128) ? ew[(it * 128 + c2) * 260 + k]
                             : ew[(it * 128 + (c2 - 128)) * 260 + 128 + k];
        (it ? g_WpT1 : g_WpT0)[k * 256 + c2] = v; return;
    }
    i -= B;
    if (i < C) {
        int it = i / (128 * 4); int r = i % (128 * 4);
        (it ? g_WeP1 : g_WeP0)[r] = ew[(it * 128 + r / 4) * 260 + 256 + (r & 3)]; return;
    }
    i -= C;
    if (i < D) { int k = i / 128, c = i % 128; g_WskipT[i] = wskip[c * 128 + k]; return; }
    i -= D;
    if (i < E) { int k = i / 128, c = i % 128; g_WgeoT[i]  = wgeo[c * 128 + k]; return; }
    i -= E;
    if (i < F) { int j = i / 128, c = i % 128; g_W2T[i] = w2[c * 384 + j]; return; }
    i -= F;
    if (i < G) { int j = i / 128, c = i % 128; g_WgT[i] = wg2[c * 128 + j]; return; }
}

// ---------------- CSR build ----------------
__global__ void k_hist(const int* __restrict__ eidx) {
    int e = blockIdx.x * 256 + threadIdx.x;
    if (e < N_EDGES) atomicAdd(&g_deg[eidx[2 * e]], 1);
}

// Block scan + single atomic base grab. Offset placement is nondeterministic
// across runs, but per-node edge sets are identical and fmax is order/placement
// invariant, so all outputs are bit-deterministic.
__global__ void k_assign() {
    __shared__ int wsum[8];
    __shared__ int sbase;
    int i = blockIdx.x * 256 + threadIdx.x;
    int d = (i < N_NODES) ? g_deg[i] : 0;
    int lane = threadIdx.x & 31, w = threadIdx.x >> 5;
    int p = d;
#pragma unroll
    for (int o = 1; o < 32; o <<= 1) {
        int v = __shfl_up_sync(0xffffffffu, p, o);
        if (lane >= o) p += v;
    }
    if (lane == 31) wsum[w] = p;
    __syncthreads();
    if (threadIdx.x == 0) {
        int s = 0;
#pragma unroll
        for (int k = 0; k < 8; k++) { int t = wsum[k]; wsum[k] = s; s += t; }
        sbase = atomicAdd(&g_ctr, s);
    }
    __syncthreads();
    int off = sbase + wsum[w] + p - d;   // exclusive prefix within grid chunk
    if (i < N_NODES) { g_off[i] = off; g_pos[i] = off; }
}

__global__ void k_sort(const int* __restrict__ eidx, const float* __restrict__ etype) {
    int e = blockIdx.x * 256 + threadIdx.x;
    if (e < N_EDGES) {
        int f = eidx[2 * e], to = eidx[2 * e + 1];
        int slot = atomicAdd(&g_pos[f], 1);
        g_toS[slot] = to;
        g_efS[slot] = *(const float4*)(etype + 4 * e);
    }
}

// ---------------- f32x2 GEMM (nodes x K) @ (K x COUT) ----------------
enum { XS_EXT = 0, XS_CF0 = 1, XS_CF1 = 2 };
enum { WS_OP = 0, WS_P0 = 1, WS_P1 = 2, WS_SKIP = 3, WS_GEO = 4 };
enum { YS_CF0 = 0, YS_P = 1 };

__device__ __forceinline__ const float* sel_x(int s, const float* ext) {
    if (s == XS_CF0) return g_cf0;
    if (s == XS_CF1) return g_cf1;
    return ext;
}
__device__ __forceinline__ const float* sel_w(int s) {
    switch (s) {
        case WS_OP:   return g_WopT;
        case WS_P0:   return g_WpT0;
        case WS_P1:   return g_WpT1;
        case WS_SKIP: return g_WskipT;
        default:      return g_WgeoT;
    }
}
__device__ __forceinline__ float* sel_y(int s) { return (s == YS_CF0) ? g_cf0 : g_P; }

template<int K, int COUT, bool STORE, bool HASBIAS, bool EXISTS, bool COLMAX>
__global__ void __launch_bounds__(256)
k_gemm(const float* __restrict__ Xext, int xsel, int wsel,
       const float* __restrict__ bias, const float* __restrict__ exists,
       int ysel, int slot) {
    constexpr int CH_T = COUT / 8;       // threads along channel dim
    constexpr int ND_T = 256 / CH_T;     // threads along node dim
    constexpr int TN   = ND_T * 4;       // nodes per block
    constexpr int XP   = TN + 6;         // u64 pitch: stride 2*(TN+6) words ≡ 12 mod 32
    constexpr int NKC  = (K + 31) / 32;

    __shared__ __align__(16) float sW[32 * COUT];
    __shared__ __align__(16) u64   sX2[32 * XP];
    __shared__ __align__(16) float sRed[COLMAX ? ND_T * COUT : 4];

    const float* X  = sel_x(xsel, Xext);
    const float* Wt = sel_w(wsel);

    int tid = threadIdx.x;
    int ct = tid % CH_T, nt = tid / CH_T;
    int nb = blockIdx.x * TN;

    u64 acc2[4][4];
#pragma unroll
    for (int c = 0; c < 4; c++)
#pragma unroll
        for (int n = 0; n < 4; n++) acc2[c][n] = 0ull;

    for (int kc = 0; kc < NKC; kc++) {
        int k0 = kc * 32;
        // --- stage W: float4 vectorized, row-wise k guard ---
#pragma unroll
        for (int p = 0; p < COUT * 8 / 256; p++) {
            int idx4 = tid + p * 256;
            int c4 = idx4 % (COUT / 4), kk = idx4 / (COUT / 4);
            int k = k0 + kk;
            float4 wv = make_float4(0.f, 0.f, 0.f, 0.f);
            if (k < K) wv = *(const float4*)(Wt + k * COUT + c4 * 4);
            *(float4*)(sW + kk * COUT + c4 * 4) = wv;
        }
        // --- stage X as duplicated (x,x) u64 pairs ---
        if (K % 4 == 0) {
#pragma unroll
            for (int p = 0; p < TN * 8 / 256; p++) {
                int idx4 = tid + p * 256;
                int kq = idx4 & 7, n = idx4 >> 3;
                int node = nb + n;
                float4 xv = make_float4(0.f, 0.f, 0.f, 0.f);
                if (node < N_NODES) xv = *(const float4*)(X + node * K + k0 + kq * 4);
                sX2[(kq * 4 + 0) * XP + n] = pack2(xv.x, xv.x);
                sX2[(kq * 4 + 1) * XP + n] = pack2(xv.y, xv.y);
                sX2[(kq * 4 + 2) * XP + n] = pack2(xv.z, xv.z);
                sX2[(kq * 4 + 3) * XP + n] = pack2(xv.w, xv.w);
            }
        } else {
#pragma unroll
            for (int p = 0; p < TN * 32 / 256; p++) {
                int idx = tid + p * 256;
                int kk = idx & 31, n = idx >> 5;
                int node = nb + n, k = k0 + kk;
                float v = (node < N_NODES && k < K) ? X[node * K + k] : 0.f;
                sX2[kk * XP + n] = pack2(v, v);
            }
        }
        __syncthreads();
#pragma unroll
        for (int kk = 0; kk < 32; kk++) {
            const u64* wrow = reinterpret_cast<const u64*>(sW + kk * COUT) + ct * 4;
            ulonglong2 wa = *reinterpret_cast<const ulonglong2*>(wrow);
            ulonglong2 wb = *reinterpret_cast<const ulonglong2*>(wrow + 2);
            const u64* xrow = sX2 + kk * XP + nt * 4;
            ulonglong2 xa = *reinterpret_cast<const ulonglong2*>(xrow);
            ulonglong2 xb = *reinterpret_cast<const ulonglong2*>(xrow + 2);
            u64 w_[4] = { wa.x, wa.y, wb.x, wb.y };
            u64 x_[4] = { xa.x, xa.y, xb.x, xb.y };
#pragma unroll
            for (int c = 0; c < 4; c++)
#pragma unroll
                for (int n = 0; n < 4; n++)
                    acc2[c][n] = fma2(w_[c], x_[n], acc2[c][n]);
        }
        __syncthreads();
    }

    // epilogue
    float b[8];
#pragma unroll
    for (int c = 0; c < 8; c++) b[c] = HASBIAS ? bias[ct * 8 + c] : 0.f;
    float lmax[8];
#pragma unroll
    for (int c = 0; c < 8; c++) lmax[c] = -3.402823466e38f;

    float* Y = STORE ? sel_y(ysel) : nullptr;
#pragma unroll
    for (int n = 0; n < 4; n++) {
        int node = nb + nt * 4 + n;
        if (node < N_NODES) {
            float ex = EXISTS ? exists[node] : 1.f;
            float y[8];
#pragma unroll
            for (int cp = 0; cp < 4; cp++)
                unpack2(acc2[cp][n], y[2 * cp], y[2 * cp + 1]);
#pragma unroll
            for (int c = 0; c < 8; c++) {
                float v = y[c] + b[c];
                if (EXISTS) v *= ex;
                y[c] = v;
                if (COLMAX) lmax[c] = fmaxf(lmax[c], v);
            }
            if (STORE) {
                float4 y0 = { y[0], y[1], y[2], y[3] };
                float4 y1 = { y[4], y[5], y[6], y[7] };
                *(float4*)(Y + node * COUT + ct * 8)     = y0;
                *(float4*)(Y + node * COUT + ct * 8 + 4) = y1;
            }
        }
    }

    if (COLMAX) {
#pragma unroll
        for (int c = 0; c < 8; c++) sRed[nt * COUT + ct * 8 + c] = lmax[c];
        __syncthreads();
        for (int c = tid; c < COUT; c += 256) {
            float m = sRed[c];
#pragma unroll
            for (int r = 1; r < ND_T; r++) m = fmaxf(m, sRed[r * COUT + c]);
            atomicMax(&g_keys[slot * 128 + c], fkey(m));
        }
    }
}

// ---------------- per-node gather + max (replaces scatter-max) ----------------
template<bool STORE>
__global__ void __launch_bounds__(512)
k_edge(const float* __restrict__ eb, int wesel, int slot) {
    const float* WeP = wesel ? g_WeP1 : g_WeP0;
    int warp = threadIdx.x >> 5, lane = threadIdx.x & 31;
    int v = blockIdx.x * 16 + warp;
    __shared__ __align__(16) float sRed[16 * 128];

    float4 acc = make_float4(0.f, 0.f, 0.f, 0.f);   // scatter-init-zero semantics
    if (v < N_NODES) {
        const float4* P4 = (const float4*)g_P;
        float4 pa = P4[v * 64 + lane];
        float4 b4 = *(const float4*)(eb + lane * 4);
        float4 base = { pa.x + b4.x, pa.y + b4.y, pa.z + b4.z, pa.w + b4.w };
        const float4* We4 = (const float4*)WeP;
        float4 we0 = We4[lane * 4 + 0];
        float4 we1 = We4[lane * 4 + 1];
        float4 we2 = We4[lane * 4 + 2];
        float4 we3 = We4[lane * 4 + 3];
        int start = g_off[v], deg = g_deg[v];
#pragma unroll 2
        for (int j = 0; j < deg; j++) {
            int to = g_toS[start + j];
            float4 ef = g_efS[start + j];
            float4 pb = P4[to * 64 + 32 + lane];
            float d0 = fmaf(we0.x, ef.x, fmaf(we0.y, ef.y, fmaf(we0.z, ef.z, we0.w * ef.w)));
            float d1 = fmaf(we1.x, ef.x, fmaf(we1.y, ef.y, fmaf(we1.z, ef.z, we1.w * ef.w)));
            float d2 = fmaf(we2.x, ef.x, fmaf(we2.y, ef.y, fmaf(we2.z, ef.z, we2.w * ef.w)));
            float d3 = fmaf(we3.x, ef.x, fmaf(we3.y, ef.y, fmaf(we3.z, ef.z, we3.w * ef.w)));
            float v0 = base.x + pb.x + d0;
            float v1 = base.y + pb.y + d1;
            float v2 = base.z + pb.z + d2;
            float v3 = base.w + pb.w + d3;
            acc.x = fmaxf(acc.x, fmaxf(v0, 0.01f * v0));
            acc.y = fmaxf(acc.y, fmaxf(v1, 0.01f * v1));
            acc.z = fmaxf(acc.z, fmaxf(v2, 0.01f * v2));
            acc.w = fmaxf(acc.w, fmaxf(v3, 0.01f * v3));
        }
        if (STORE) *(float4*)(g_cf1 + v * 128 + lane * 4) = acc;
    }
    *(float4*)(sRed + warp * 128 + lane * 4) = acc;
    __syncthreads();
    int t = threadIdx.x;
    if (t < 128) {
        float m = sRed[t];
#pragma unroll
        for (int r = 1; r < 16; r++) m = fmaxf(m, sRed[r * 128 + t]);
        atomicMax(&g_keys[slot * 128 + t], fkey(m));
    }
}

// ---------------- finalize: tiny GEMMs + group norm ----------------
__global__ void __launch_bounds__(384)
k_final(const float* __restrict__ second_b, const float* __restrict__ sgeo_b,
        const float* __restrict__ gnw, const float* __restrict__ gnb,
        float* __restrict__ out) {
    __shared__ float spf[384];
    __shared__ float spg[128];
    int t = threadIdx.x;
    if (t < 384) spf[t] = fdec(g_keys[t]);              // slots 0..2 concatenated
    if (t < 128) spg[t] = leaky(fdec(g_keys[512 + t])); // pg = leaky(max cg), slot 4
    __syncthreads();
    if (t < 128) {
        float a = 0.f;
#pragma unroll 4
        for (int j = 0; j < 384; j++) a = fmaf(spf[j], g_W2T[j * 128 + t], a);
        a += second_b[t];
        out[t] = leaky(a);

        float g = 0.f;
#pragma unroll 4
        for (int j = 0; j < 128; j++) g = fmaf(spg[j], g_WgT[j * 128 + t], g);
        g += sgeo_b[t];

        // group norm: 16 groups of 8 contiguous channels -> shfl within 8-lane segments
        float s = g;
        s += __shfl_xor_sync(0xffffffffu, s, 1, 8);
        s += __shfl_xor_sync(0xffffffffu, s, 2, 8);
        s += __shfl_xor_sync(0xffffffffu, s, 4, 8);
        float mu = s * 0.125f;
        float d = g - mu;
        float q = d * d;
        q += __shfl_xor_sync(0xffffffffu, q, 1, 8);
        q += __shfl_xor_sync(0xffffffffu, q, 2, 8);
        q += __shfl_xor_sync(0xffffffffu, q, 4, 8);
        float var = q * 0.125f;
        float xn = d * rsqrtf(var + 1e-5f);
        float y = xn * gnw[t] + gnb[t];
        float sgv = fdec(g_keys[384 + t]);              // slot 3 = skip max
        float o = leaky(sgv) + y;
        out[128 + t] = leaky(o);
    }
}

// ---------------- host launcher ----------------
static cudaStream_t s_csr = 0, s_geo = 0;
static cudaEvent_t evInit = 0, evPrep = 0, evCsr = 0, evGeo = 0;

extern "C" void kernel_launch(void* const* d_in, const int* in_sizes, int n_in,
                              void* d_out, int out_size) {
    const float* child_feats = (const float*)d_in[0];
    const float* child_geo   = (const float*)d_in[1];
    const float* exists      = (const float*)d_in[2];
    const float* etype       = (const float*)d_in[3];
    const int*   eidx        = (const int*)d_in[4];
    const float* wop   = (const float*)d_in[5];
    const float* bop   = (const float*)d_in[6];
    const float* w2    = (const float*)d_in[7];
    const float* b2    = (const float*)d_in[8];
    const float* ew    = (const float*)d_in[9];
    const float* ebias = (const float*)d_in[10];
    const float* wgeo  = (const float*)d_in[11];
    const float* bgeo  = (const float*)d_in[12];
    const float* wg2   = (const float*)d_in[13];
    const float* bg2   = (const float*)d_in[14];
    const float* gnw   = (const float*)d_in[15];
    const float* gnb   = (const float*)d_in[16];
    const float* wskip = (const float*)d_in[17];
    const float* bskip = (const float*)d_in[18];
    float* out = (float*)d_out;

    (void)in_sizes; (void)n_in; (void)out_size;

    // one-time host-side resources (created on the uncaptured correctness call)
    if (!s_csr) {
        cudaStreamCreateWithFlags(&s_csr, cudaStreamNonBlocking);
        cudaStreamCreateWithFlags(&s_geo, cudaStreamNonBlocking);
        cudaEventCreateWithFlags(&evInit, cudaEventDisableTiming);
        cudaEventCreateWithFlags(&evPrep, cudaEventDisableTiming);
        cudaEventCreateWithFlags(&evCsr,  cudaEventDisableTiming);
        cudaEventCreateWithFlags(&evGeo,  cudaEventDisableTiming);
    }

    // main stream: init + weight packing
    k_init<<<(N_NODES + 255) / 256, 256>>>();
    cudaEventRecord(evInit, 0);
    {
        const int total = FIN * 128 + 2 * 128 * 256 + 2 * 128 * 4
                        + 128 * 128 + 128 * 128 + 384 * 128 + 128 * 128;
        k_prep<<<(total + 255) / 256, 256>>>(wop, ew, wskip, wgeo, w2, wg2);
    }
    cudaEventRecord(evPrep, 0);

    // CSR stream (needs g_deg/g_ctr zeroed by k_init)
    cudaStreamWaitEvent(s_csr, evInit, 0);
    k_hist<<<(N_EDGES + 255) / 256, 256, 0, s_csr>>>(eidx);
    k_assign<<<(N_NODES + 255) / 256, 256, 0, s_csr>>>();
    k_sort<<<(N_EDGES + 255) / 256, 256, 0, s_csr>>>(eidx, etype);
    cudaEventRecord(evCsr, s_csr);

    // geo stream (needs packed weights + g_keys init)
    cudaStreamWaitEvent(s_geo, evPrep, 0);
    k_gemm<128, 128, false, true, true, true><<<(N_NODES + 63) / 64, 256, 0, s_geo>>>(
        child_geo, XS_EXT, WS_SKIP, bskip, exists, YS_CF0, 3);
    k_gemm<128, 128, false, true, true, true><<<(N_NODES + 63) / 64, 256, 0, s_geo>>>(
        child_geo, XS_EXT, WS_GEO, bgeo, exists, YS_CF0, 4);
    cudaEventRecord(evGeo, s_geo);

    // main chain: cf0 = (child_feats @ Wop^T + b) * exists ; col-max -> slot 0
    k_gemm<FIN, 128, true, true, true, true><<<(N_NODES + 63) / 64, 256>>>(
        child_feats, XS_EXT, WS_OP, bop, exists, YS_CF0, 0);

    // iteration 0
    k_gemm<128, 256, true, false, false, false><<<N_NODES / 32, 256>>>(
        nullptr, XS_CF0, WS_P0, nullptr, nullptr, YS_P, 0);
    cudaStreamWaitEvent(0, evCsr, 0);
    k_edge<true><<<N_NODES / 16, 512>>>(ebias, 0, 1);

    // iteration 1
    k_gemm<128, 256, true, false, false, false><<<N_NODES / 32, 256>>>(
        nullptr, XS_CF1, WS_P1, nullptr, nullptr, YS_P, 0);
    k_edge<false><<<N_NODES / 16, 512>>>(ebias + 128, 1, 2);

    // finalize (needs geo col-maxes)
    cudaStreamWaitEvent(0, evGeo, 0);
    k_final<<<1, 384>>>(b2, bg2, gnw, gnb, out);
}

// round 7
// speedup vs baseline: 1.4621x; 1.3183x over previous
#include <cuda_runtime.h>
#include <math.h>

#define N_NODES 20000
#define N_EDGES 320000
#define HDIM 128
#define FIN 162

typedef unsigned long long u64;

// ---------------- device scratch (static, no allocation) ----------------
__device__ float g_cf0[N_NODES * HDIM];
__device__ float g_cf1[N_NODES * HDIM];
__device__ float g_P[N_NODES * 2 * HDIM];

__device__ int   g_deg[N_NODES];
__device__ int   g_off[N_NODES];
__device__ int   g_pos[N_NODES];
__device__ int   g_ctr;
__device__ int   g_toS[N_EDGES];
__device__ float4 g_efS[N_EDGES];

// col-max key slots: 0,1,2 = parent feats per iter; 3 = skip max; 4 = cg max
__device__ unsigned g_keys[5 * 128];

// packed / transposed weights
__device__ float g_WopT[FIN * 128];      // [k][c]
__device__ float g_WpT0[128 * 256];      // [k][c2]  (Wa|Wb iter0)
__device__ float g_WpT1[128 * 256];
__device__ float g_WeP0[128 * 4];        // [c][t]
__device__ float g_WeP1[128 * 4];
__device__ float g_WskipT[128 * 128];
__device__ float g_WgeoT[128 * 128];
__device__ float g_W2T[384 * 128];       // second_w transposed [j][c]
__device__ float g_WgT[128 * 128];       // second_geo_w transposed [j][c]

// ---------------- helpers ----------------
__device__ __forceinline__ unsigned fkey(float f) {
    unsigned u = __float_as_uint(f);
    return (u & 0x80000000u) ? ~u : (u | 0x80000000u);
}
__device__ __forceinline__ float fdec(unsigned k) {
    unsigned u = (k & 0x80000000u) ? (k & 0x7fffffffu) : ~k;
    return __uint_as_float(u);
}
__device__ __forceinline__ float leaky(float x) { return fmaxf(x, 0.01f * x); }

__device__ __forceinline__ u64 pack2(float lo, float hi) {
    u64 r; asm("mov.b64 %0, {%1, %2};" : "=l"(r) : "f"(lo), "f"(hi)); return r;
}
__device__ __forceinline__ void unpack2(u64 v, float& lo, float& hi) {
    asm("mov.b64 {%0, %1}, %2;" : "=f"(lo), "=f"(hi) : "l"(v));
}
__device__ __forceinline__ u64 fma2(u64 a, u64 b, u64 c) {
    u64 d; asm("fma.rn.f32x2 %0, %1, %2, %3;" : "=l"(d) : "l"(a), "l"(b), "l"(c)); return d;
}

// ---------------- init ----------------
__global__ void k_init() {
    int i = blockIdx.x * 256 + threadIdx.x;
    if (i < N_NODES) g_deg[i] = 0;
    if (i < 5 * 128) g_keys[i] = fkey(-3.402823466e38f);
    if (i == 0) g_ctr = 0;
}

// ---------------- weight pack / transpose ----------------
__global__ void k_prep(const float* __restrict__ wop, const float* __restrict__ ew,
                       const float* __restrict__ wskip, const float* __restrict__ wgeo,
                       const float* __restrict__ w2, const float* __restrict__ wg2) {
    int i = blockIdx.x * 256 + threadIdx.x;
    const int A = FIN * 128;
    const int B = 2 * 128 * 256;
    const int C = 2 * 128 * 4;
    const int D = 128 * 128;
    const int E = 128 * 128;
    const int F = 384 * 128;
    const int G = 128 * 128;
    if (i < A) { int k = i / 128, c = i % 128; g_WopT[i] = wop[c * FIN + k]; return; }
    i -= A;
    if (i < B) {
        int it = i / (128 * 256); int r = i % (128 * 256);
        int k = r / 256, c2 = r % 256;
        float v = (c2 < 128) ? ew[(it * 128 + c2) * 260 + k]
                             : ew[(it * 128 + (c2 - 128)) * 260 + 128 + k];
        (it ? g_WpT1 : g_WpT0)[k * 256 + c2] = v; return;
    }
    i -= B;
    if (i < C) {
        int it = i / (128 * 4); int r = i % (128 * 4);
        (it ? g_WeP1 : g_WeP0)[r] = ew[(it * 128 + r / 4) * 260 + 256 + (r & 3)]; return;
    }
    i -= C;
    if (i < D) { int k = i / 128, c = i % 128; g_WskipT[i] = wskip[c * 128 + k]; return; }
    i -= D;
    if (i < E) { int k = i / 128, c = i % 128; g_WgeoT[i]  = wgeo[c * 128 + k]; return; }
    i -= E;
    if (i < F) { int j = i / 128, c = i % 128; g_W2T[i] = w2[c * 384 + j]; return; }
    i -= F;
    if (i < G) { int j = i / 128, c = i % 128; g_WgT[i] = wg2[c * 128 + j]; return; }
}

// ---------------- CSR build ----------------
__global__ void k_hist(const int* __restrict__ eidx) {
    int e = blockIdx.x * 256 + threadIdx.x;
    if (e < N_EDGES) atomicAdd(&g_deg[eidx[2 * e]], 1);
}

// Block scan + single atomic base grab. Offset placement is nondeterministic
// across runs, but per-node edge sets are identical and fmax is order/placement
// invariant, so all outputs are bit-deterministic.
__global__ void k_assign() {
    __shared__ int wsum[8];
    __shared__ int sbase;
    int i = blockIdx.x * 256 + threadIdx.x;
    int d = (i < N_NODES) ? g_deg[i] : 0;
    int lane = threadIdx.x & 31, w = threadIdx.x >> 5;
    int p = d;
#pragma unroll
    for (int o = 1; o < 32; o <<= 1) {
        int v = __shfl_up_sync(0xffffffffu, p, o);
        if (lane >= o) p += v;
    }
    if (lane == 31) wsum[w] = p;
    __syncthreads();
    if (threadIdx.x == 0) {
        int s = 0;
#pragma unroll
        for (int k = 0; k < 8; k++) { int t = wsum[k]; wsum[k] = s; s += t; }
        sbase = atomicAdd(&g_ctr, s);
    }
    __syncthreads();
    int off = sbase + wsum[w] + p - d;   // exclusive prefix within grid chunk
    if (i < N_NODES) { g_off[i] = off; g_pos[i] = off; }
}

__global__ void k_sort(const int* __restrict__ eidx, const float* __restrict__ etype) {
    int e = blockIdx.x * 256 + threadIdx.x;
    if (e < N_EDGES) {
        int f = eidx[2 * e], to = eidx[2 * e + 1];
        int slot = atomicAdd(&g_pos[f], 1);
        g_toS[slot] = to;
        g_efS[slot] = *(const float4*)(etype + 4 * e);
    }
}

// ---------------- f32x2 GEMM (nodes x K) @ (K x COUT) ----------------
// Thread tile: 8 channels (as 4 f32x2 pairs) x 8 nodes.
// W stored in smem interleaved so each lane's channel-pair reads are
// CONSECUTIVE u64s per j (conflict-free):
//   u64 index(kk, j, ct) = kk*COUT/2 + j*CH_T + ct ,  channels = ct*8 + j*2 + {0,1}
// X stored as duplicated (x,x) u64 pairs; reads are warp-broadcast.
enum { XS_EXT = 0, XS_CF0 = 1, XS_CF1 = 2 };
enum { WS_OP = 0, WS_P0 = 1, WS_P1 = 2, WS_SKIP = 3, WS_GEO = 4 };
enum { YS_CF0 = 0, YS_P = 1 };

__device__ __forceinline__ const float* sel_x(int s, const float* ext) {
    if (s == XS_CF0) return g_cf0;
    if (s == XS_CF1) return g_cf1;
    return ext;
}
__device__ __forceinline__ const float* sel_w(int s) {
    switch (s) {
        case WS_OP:   return g_WopT;
        case WS_P0:   return g_WpT0;
        case WS_P1:   return g_WpT1;
        case WS_SKIP: return g_WskipT;
        default:      return g_WgeoT;
    }
}
__device__ __forceinline__ float* sel_y(int s) { return (s == YS_CF0) ? g_cf0 : g_P; }

template<int K, int COUT, bool STORE, bool HASBIAS, bool EXISTS, bool COLMAX>
__global__ void __launch_bounds__(256)
k_gemm(const float* __restrict__ Xext, int xsel, int wsel,
       const float* __restrict__ bias, const float* __restrict__ exists,
       int ysel, int slot) {
    constexpr int CH_T = COUT / 8;       // threads along channel dim (16 or 32)
    constexpr int ND_T = 256 / CH_T;     // thread-rows along node dim (16 or 8)
    constexpr int TN   = ND_T * 8;       // nodes per block (128 or 64)
    constexpr int XP   = TN + 2;         // u64 pitch (even -> 16B-aligned rows)
    constexpr int NKC  = (K + 31) / 32;

    __shared__ __align__(16) float sW[32 * COUT];
    __shared__ __align__(16) u64   sX2[32 * XP];
    __shared__ __align__(16) float sRed[COLMAX ? ND_T * COUT : 4];

    const float* X  = sel_x(xsel, Xext);
    const float* Wt = sel_w(wsel);

    int tid = threadIdx.x;
    int ct = tid % CH_T, nt = tid / CH_T;
    int nb = blockIdx.x * TN;

    u64* sW64 = reinterpret_cast<u64*>(sW);

    u64 acc2[4][8];
#pragma unroll
    for (int c = 0; c < 4; c++)
#pragma unroll
        for (int n = 0; n < 8; n++) acc2[c][n] = 0ull;

    for (int kc = 0; kc < NKC; kc++) {
        int k0 = kc * 32;
        // --- stage W into interleaved pair layout (float4 loads, u64 stores) ---
#pragma unroll
        for (int p = 0; p < COUT * 8 / 256; p++) {
            int idx4 = tid + p * 256;
            int c4 = idx4 % (COUT / 4), kk = idx4 / (COUT / 4);
            int k = k0 + kk;
            float4 wv = make_float4(0.f, 0.f, 0.f, 0.f);
            if (k < K) wv = *(const float4*)(Wt + k * COUT + c4 * 4);
            int c = c4 * 4;
            int ct0 = c >> 3;
            int j0  = (c & 7) >> 1;          // 0 or 2
            int base = kk * (COUT / 2) + ct0;
            sW64[base + j0 * CH_T]       = pack2(wv.x, wv.y);
            sW64[base + (j0 + 1) * CH_T] = pack2(wv.z, wv.w);
        }
        // --- stage X as duplicated (x,x) u64 pairs ---
        if (K % 32 == 0) {
#pragma unroll
            for (int p = 0; p < TN * 8 / 256; p++) {
                int idx4 = tid + p * 256;
                int kq = idx4 & 7, n = idx4 >> 3;
                int node = nb + n;
                float4 xv = make_float4(0.f, 0.f, 0.f, 0.f);
                if (node < N_NODES) xv = *(const float4*)(X + node * K + k0 + kq * 4);
                sX2[(kq * 4 + 0) * XP + n] = pack2(xv.x, xv.x);
                sX2[(kq * 4 + 1) * XP + n] = pack2(xv.y, xv.y);
                sX2[(kq * 4 + 2) * XP + n] = pack2(xv.z, xv.z);
                sX2[(kq * 4 + 3) * XP + n] = pack2(xv.w, xv.w);
            }
        } else {
#pragma unroll
            for (int p = 0; p < TN * 32 / 256; p++) {
                int idx = tid + p * 256;
                int kk = idx & 31, n = idx >> 5;
                int node = nb + n, k = k0 + kk;
                float v = (node < N_NODES && k < K) ? X[node * K + k] : 0.f;
                sX2[kk * XP + n] = pack2(v, v);
            }
        }
        __syncthreads();
#pragma unroll 8
        for (int kk = 0; kk < 32; kk++) {
            int wb = kk * (COUT / 2) + ct;
            u64 w_[4];
#pragma unroll
            for (int j = 0; j < 4; j++) w_[j] = sW64[wb + j * CH_T];
            const ulonglong2* xr = reinterpret_cast<const ulonglong2*>(sX2 + kk * XP + nt * 8);
            ulonglong2 xa = xr[0], xb = xr[1], xc = xr[2], xd = xr[3];
            u64 x_[8] = { xa.x, xa.y, xb.x, xb.y, xc.x, xc.y, xd.x, xd.y };
#pragma unroll
            for (int j = 0; j < 4; j++)
#pragma unroll
                for (int n = 0; n < 8; n++)
                    acc2[j][n] = fma2(w_[j], x_[n], acc2[j][n]);
        }
        __syncthreads();
    }

    // epilogue (channel order within thread is ct*8 + [0..7], same as pair order)
    float b[8];
#pragma unroll
    for (int c = 0; c < 8; c++) b[c] = HASBIAS ? bias[ct * 8 + c] : 0.f;
    float lmax[8];
#pragma unroll
    for (int c = 0; c < 8; c++) lmax[c] = -3.402823466e38f;

    float* Y = STORE ? sel_y(ysel) : nullptr;
#pragma unroll
    for (int n = 0; n < 8; n++) {
        int node = nb + nt * 8 + n;
        if (node < N_NODES) {
            float ex = EXISTS ? exists[node] : 1.f;
            float y[8];
#pragma unroll
            for (int cp = 0; cp < 4; cp++)
                unpack2(acc2[cp][n], y[2 * cp], y[2 * cp + 1]);
#pragma unroll
            for (int c = 0; c < 8; c++) {
                float v = y[c] + b[c];
                if (EXISTS) v *= ex;
                y[c] = v;
                if (COLMAX) lmax[c] = fmaxf(lmax[c], v);
            }
            if (STORE) {
                float4 y0 = { y[0], y[1], y[2], y[3] };
                float4 y1 = { y[4], y[5], y[6], y[7] };
                *(float4*)(Y + node * COUT + ct * 8)     = y0;
                *(float4*)(Y + node * COUT + ct * 8 + 4) = y1;
            }
        }
    }

    if (COLMAX) {
#pragma unroll
        for (int c = 0; c < 8; c++) sRed[nt * COUT + ct * 8 + c] = lmax[c];
        __syncthreads();
        for (int c = tid; c < COUT; c += 256) {
            float m = sRed[c];
#pragma unroll
            for (int r = 1; r < ND_T; r++) m = fmaxf(m, sRed[r * COUT + c]);
            atomicMax(&g_keys[slot * 128 + c], fkey(m));
        }
    }
}

// ---------------- per-node gather + max (replaces scatter-max) ----------------
template<bool STORE>
__global__ void __launch_bounds__(512)
k_edge(const float* __restrict__ eb, int wesel, int slot) {
    const float* WeP = wesel ? g_WeP1 : g_WeP0;
    int warp = threadIdx.x >> 5, lane = threadIdx.x & 31;
    int v = blockIdx.x * 16 + warp;
    __shared__ __align__(16) float sRed[16 * 128];

    float4 acc = make_float4(0.f, 0.f, 0.f, 0.f);   // scatter-init-zero semantics
    if (v < N_NODES) {
        const float4* P4 = (const float4*)g_P;
        float4 pa = P4[v * 64 + lane];
        float4 b4 = *(const float4*)(eb + lane * 4);
        float4 base = { pa.x + b4.x, pa.y + b4.y, pa.z + b4.z, pa.w + b4.w };
        const float4* We4 = (const float4*)WeP;
        float4 we0 = We4[lane * 4 + 0];
        float4 we1 = We4[lane * 4 + 1];
        float4 we2 = We4[lane * 4 + 2];
        float4 we3 = We4[lane * 4 + 3];
        int start = g_off[v], deg = g_deg[v];
#pragma unroll 4
        for (int j = 0; j < deg; j++) {
            int to = g_toS[start + j];
            float4 ef = g_efS[start + j];
            float4 pb = P4[to * 64 + 32 + lane];
            float d0 = fmaf(we0.x, ef.x, fmaf(we0.y, ef.y, fmaf(we0.z, ef.z, we0.w * ef.w)));
            float d1 = fmaf(we1.x, ef.x, fmaf(we1.y, ef.y, fmaf(we1.z, ef.z, we1.w * ef.w)));
            float d2 = fmaf(we2.x, ef.x, fmaf(we2.y, ef.y, fmaf(we2.z, ef.z, we2.w * ef.w)));
            float d3 = fmaf(we3.x, ef.x, fmaf(we3.y, ef.y, fmaf(we3.z, ef.z, we3.w * ef.w)));
            float v0 = base.x + pb.x + d0;
            float v1 = base.y + pb.y + d1;
            float v2 = base.z + pb.z + d2;
            float v3 = base.w + pb.w + d3;
            acc.x = fmaxf(acc.x, fmaxf(v0, 0.01f * v0));
            acc.y = fmaxf(acc.y, fmaxf(v1, 0.01f * v1));
            acc.z = fmaxf(acc.z, fmaxf(v2, 0.01f * v2));
            acc.w = fmaxf(acc.w, fmaxf(v3, 0.01f * v3));
        }
        if (STORE) *(float4*)(g_cf1 + v * 128 + lane * 4) = acc;
    }
    *(float4*)(sRed + warp * 128 + lane * 4) = acc;
    __syncthreads();
    int t = threadIdx.x;
    if (t < 128) {
        float m = sRed[t];
#pragma unroll
        for (int r = 1; r < 16; r++) m = fmaxf(m, sRed[r * 128 + t]);
        atomicMax(&g_keys[slot * 128 + t], fkey(m));
    }
}

// ---------------- finalize: tiny GEMMs + group norm ----------------
__global__ void __launch_bounds__(384)
k_final(const float* __restrict__ second_b, const float* __restrict__ sgeo_b,
        const float* __restrict__ gnw, const float* __restrict__ gnb,
        float* __restrict__ out) {
    __shared__ float spf[384];
    __shared__ float spg[128];
    int t = threadIdx.x;
    if (t < 384) spf[t] = fdec(g_keys[t]);              // slots 0..2 concatenated
    if (t < 128) spg[t] = leaky(fdec(g_keys[512 + t])); // pg = leaky(max cg), slot 4
    __syncthreads();
    if (t < 128) {
        float a = 0.f;
#pragma unroll 4
        for (int j = 0; j < 384; j++) a = fmaf(spf[j], g_W2T[j * 128 + t], a);
        a += second_b[t];
        out[t] = leaky(a);

        float g = 0.f;
#pragma unroll 4
        for (int j = 0; j < 128; j++) g = fmaf(spg[j], g_WgT[j * 128 + t], g);
        g += sgeo_b[t];

        // group norm: 16 groups of 8 contiguous channels -> shfl within 8-lane segments
        float s = g;
        s += __shfl_xor_sync(0xffffffffu, s, 1, 8);
        s += __shfl_xor_sync(0xffffffffu, s, 2, 8);
        s += __shfl_xor_sync(0xffffffffu, s, 4, 8);
        float mu = s * 0.125f;
        float d = g - mu;
        float q = d * d;
        q += __shfl_xor_sync(0xffffffffu, q, 1, 8);
        q += __shfl_xor_sync(0xffffffffu, q, 2, 8);
        q += __shfl_xor_sync(0xffffffffu, q, 4, 8);
        float var = q * 0.125f;
        float xn = d * rsqrtf(var + 1e-5f);
        float y = xn * gnw[t] + gnb[t];
        float sgv = fdec(g_keys[384 + t]);              // slot 3 = skip max
        float o = leaky(sgv) + y;
        out[128 + t] = leaky(o);
    }
}

// ---------------- host launcher ----------------
static cudaStream_t s_csr = 0, s_geo = 0;
static cudaEvent_t evInit = 0, evPrep = 0, evCsr = 0, evGeo = 0;

extern "C" void kernel_launch(void* const* d_in, const int* in_sizes, int n_in,
                              void* d_out, int out_size) {
    const float* child_feats = (const float*)d_in[0];
    const float* child_geo   = (const float*)d_in[1];
    const float* exists      = (const float*)d_in[2];
    const float* etype       = (const float*)d_in[3];
    const int*   eidx        = (const int*)d_in[4];
    const float* wop   = (const float*)d_in[5];
    const float* bop   = (const float*)d_in[6];
    const float* w2    = (const float*)d_in[7];
    const float* b2    = (const float*)d_in[8];
    const float* ew    = (const float*)d_in[9];
    const float* ebias = (const float*)d_in[10];
    const float* wgeo  = (const float*)d_in[11];
    const float* bgeo  = (const float*)d_in[12];
    const float* wg2   = (const float*)d_in[13];
    const float* bg2   = (const float*)d_in[14];
    const float* gnw   = (const float*)d_in[15];
    const float* gnb   = (const float*)d_in[16];
    const float* wskip = (const float*)d_in[17];
    const float* bskip = (const float*)d_in[18];
    float* out = (float*)d_out;

    (void)in_sizes; (void)n_in; (void)out_size;

    // one-time host-side resources (created on the uncaptured correctness call)
    if (!s_csr) {
        cudaStreamCreateWithFlags(&s_csr, cudaStreamNonBlocking);
        cudaStreamCreateWithFlags(&s_geo, cudaStreamNonBlocking);
        cudaEventCreateWithFlags(&evInit, cudaEventDisableTiming);
        cudaEventCreateWithFlags(&evPrep, cudaEventDisableTiming);
        cudaEventCreateWithFlags(&evCsr,  cudaEventDisableTiming);
        cudaEventCreateWithFlags(&evGeo,  cudaEventDisableTiming);
    }

    // main stream: init + weight packing
    k_init<<<(N_NODES + 255) / 256, 256>>>();
    cudaEventRecord(evInit, 0);
    {
        const int total = FIN * 128 + 2 * 128 * 256 + 2 * 128 * 4
                        + 128 * 128 + 128 * 128 + 384 * 128 + 128 * 128;
        k_prep<<<(total + 255) / 256, 256>>>(wop, ew, wskip, wgeo, w2, wg2);
    }
    cudaEventRecord(evPrep, 0);

    // CSR stream (needs g_deg/g_ctr zeroed by k_init)
    cudaStreamWaitEvent(s_csr, evInit, 0);
    k_hist<<<(N_EDGES + 255) / 256, 256, 0, s_csr>>>(eidx);
    k_assign<<<(N_NODES + 255) / 256, 256, 0, s_csr>>>();
    k_sort<<<(N_EDGES + 255) / 256, 256, 0, s_csr>>>(eidx, etype);
    cudaEventRecord(evCsr, s_csr);

    // geo stream (needs packed weights + g_keys init)
    cudaStreamWaitEvent(s_geo, evPrep, 0);
    k_gemm<128, 128, false, true, true, true><<<(N_NODES + 127) / 128, 256, 0, s_geo>>>(
        child_geo, XS_EXT, WS_SKIP, bskip, exists, YS_CF0, 3);
    k_gemm<128, 128, false, true, true, true><<<(N_NODES + 127) / 128, 256, 0, s_geo>>>(
        child_geo, XS_EXT, WS_GEO, bgeo, exists, YS_CF0, 4);
    cudaEventRecord(evGeo, s_geo);

    // main chain: cf0 = (child_feats @ Wop^T + b) * exists ; col-max -> slot 0
    k_gemm<FIN, 128, true, true, true, true><<<(N_NODES + 127) / 128, 256>>>(
        child_feats, XS_EXT, WS_OP, bop, exists, YS_CF0, 0);

    // iteration 0
    k_gemm<128, 256, true, false, false, false><<<(N_NODES + 63) / 64, 256>>>(
        nullptr, XS_CF0, WS_P0, nullptr, nullptr, YS_P, 0);
    cudaStreamWaitEvent(0, evCsr, 0);
    k_edge<true><<<N_NODES / 16, 512>>>(ebias, 0, 1);

    // iteration 1
    k_gemm<128, 256, true, false, false, false><<<(N_NODES + 63) / 64, 256>>>(
        nullptr, XS_CF1, WS_P1, nullptr, nullptr, YS_P, 0);
    k_edge<false><<<N_NODES / 16, 512>>>(ebias + 128, 1, 2);

    // finalize (needs geo col-maxes)
    cudaStreamWaitEvent(0, evGeo, 0);
    k_final<<<1, 384>>>(b2, bg2, gnw, gnb, out);
}

// round 10
// speedup vs baseline: 1.7952x; 1.2279x over previous
#include <cuda_runtime.h>
#include <math.h>
#include <stdint.h>

#define N_NODES 20000
#define N_EDGES 320000
#define HDIM 128
#define FIN 162

typedef unsigned long long u64;

// ---------------- device scratch (static, no allocation) ----------------
__device__ float g_cf0[N_NODES * HDIM];
__device__ float g_cf1[N_NODES * HDIM];
__device__ float g_P[N_NODES * 2 * HDIM];

__device__ int   g_deg[N_NODES];
__device__ int   g_off[N_NODES];
__device__ int   g_pos[N_NODES];
__device__ int   g_ctr;
__device__ int   g_work[2];
__device__ int   g_toS[N_EDGES];
__device__ float4 g_efS[N_EDGES];

// col-max key slots: 0,1,2 = parent feats per iter; 3 = skip max; 4 = cg max
__device__ unsigned g_keys[5 * 128];

// packed / transposed weights
__device__ float g_WopT[FIN * 128];      // [k][c]
__device__ float g_WeP0[128 * 4];        // [c][t]
__device__ float g_WeP1[128 * 4];
__device__ float g_WskipT[128 * 128];
__device__ float g_WgeoT[128 * 128];
__device__ float g_W2T[384 * 128];       // second_w transposed [j][c]
__device__ float g_WgT[128 * 128];       // second_geo_w transposed [j][c]

// Wp bf16 hi/lo packed in mma.m16n8k16 B-fragment per-lane order:
//   index = ((s*32 + t)*32 + lane)*2 + r   (s=k-step 0..7, t=n-tile 0..31, r=reg 0..1)
//   value = bf16x2 { W[k][n], W[k+1][n] },  k = s*16 + (lane%4)*2 + r*8,  n = t*8 + lane/4
__device__ uint32_t g_Bf[2][2][16384];

// ---------------- helpers ----------------
__device__ __forceinline__ unsigned fkey(float f) {
    unsigned u = __float_as_uint(f);
    return (u & 0x80000000u) ? ~u : (u | 0x80000000u);
}
__device__ __forceinline__ float fdec(unsigned k) {
    unsigned u = (k & 0x80000000u) ? (k & 0x7fffffffu) : ~k;
    return __uint_as_float(u);
}
__device__ __forceinline__ float leaky(float x) { return fmaxf(x, 0.01f * x); }

__device__ __forceinline__ u64 pack2(float lo, float hi) {
    u64 r; asm("mov.b64 %0, {%1, %2};" : "=l"(r) : "f"(lo), "f"(hi)); return r;
}
__device__ __forceinline__ void unpack2(u64 v, float& lo, float& hi) {
    asm("mov.b64 {%0, %1}, %2;" : "=f"(lo), "=f"(hi) : "l"(v));
}
__device__ __forceinline__ u64 fma2(u64 a, u64 b, u64 c) {
    u64 d; asm("fma.rn.f32x2 %0, %1, %2, %3;" : "=l"(d) : "l"(a), "l"(b), "l"(c)); return d;
}

// bf16 split: x = hi + lo (hi = RNE bf16 of x, lo = RNE bf16 of residual)
__device__ __forceinline__ void bsplit(float x, uint32_t& hb, uint32_t& lb) {
    uint32_t u = __float_as_uint(x);
    hb = (u + 0x7FFFu + ((u >> 16) & 1u)) >> 16;
    float hf = __uint_as_float(hb << 16);
    float r = x - hf;
    uint32_t v = __float_as_uint(r);
    lb = (v + 0x7FFFu + ((v >> 16) & 1u)) >> 16;
}
// pack two floats' hi parts / lo parts into bf16x2 regs
__device__ __forceinline__ void bsplit2(float a, float b, uint32_t& h2, uint32_t& l2) {
    uint32_t ha, la, hb, lb;
    bsplit(a, ha, la); bsplit(b, hb, lb);
    h2 = ha | (hb << 16);
    l2 = la | (lb << 16);
}

__device__ __forceinline__ void mma16816(float* d, const uint32_t* a, uint32_t b0, uint32_t b1) {
    asm volatile(
        "mma.sync.aligned.m16n8k16.row.col.f32.bf16.bf16.f32 "
        "{%0,%1,%2,%3}, {%4,%5,%6,%7}, {%8,%9}, {%0,%1,%2,%3};"
        : "+f"(d[0]), "+f"(d[1]), "+f"(d[2]), "+f"(d[3])
        : "r"(a[0]), "r"(a[1]), "r"(a[2]), "r"(a[3]), "r"(b0), "r"(b1));
}

// ---------------- init ----------------
__global__ void k_init() {
    int i = blockIdx.x * 256 + threadIdx.x;
    if (i < N_NODES) g_deg[i] = 0;
    if (i < 5 * 128) g_keys[i] = fkey(-3.402823466e38f);
    if (i == 0) { g_ctr = 0; g_work[0] = 0; g_work[1] = 0; }
}

// ---------------- weight pack / transpose ----------------
__global__ void k_prep(const float* __restrict__ wop, const float* __restrict__ ew,
                       const float* __restrict__ wskip, const float* __restrict__ wgeo,
                       const float* __restrict__ w2, const float* __restrict__ wg2) {
    int i = blockIdx.x * 256 + threadIdx.x;
    const int A = FIN * 128;
    const int B = 2 * 16384;         // Wp fragment-packed entries (each writes hi+lo)
    const int C = 2 * 128 * 4;
    const int D = 128 * 128;
    const int E = 128 * 128;
    const int F = 384 * 128;
    const int G = 128 * 128;
    if (i < A) { int k = i / 128, c = i % 128; g_WopT[i] = wop[c * FIN + k]; return; }
    i -= A;
    if (i < B) {
        int it = i >> 14;
        int r14 = i & 16383;
        int r = r14 & 1;
        int l = (r14 >> 1) & 31;
        int t = (r14 >> 6) & 31;
        int s = r14 >> 11;
        int k = s * 16 + (l & 3) * 2 + r * 8;
        int n = t * 8 + (l >> 2);
        const float* row = (n < 128) ? (ew + (it * 128 + n) * 260)
                                     : (ew + (it * 128 + (n - 128)) * 260 + 128);
        float w0 = row[k], w1 = row[k + 1];
        uint32_t h2, l2; bsplit2(w0, w1, h2, l2);
        g_Bf[it][0][r14] = h2;
        g_Bf[it][1][r14] = l2;
        return;
    }
    i -= B;
    if (i < C) {
        int it = i / (128 * 4); int r = i % (128 * 4);
        (it ? g_WeP1 : g_WeP0)[r] = ew[(it * 128 + r / 4) * 260 + 256 + (r & 3)]; return;
    }
    i -= C;
    if (i < D) { int k = i / 128, c = i % 128; g_WskipT[i] = wskip[c * 128 + k]; return; }
    i -= D;
    if (i < E) { int k = i / 128, c = i % 128; g_WgeoT[i]  = wgeo[c * 128 + k]; return; }
    i -= E;
    if (i < F) { int j = i / 128, c = i % 128; g_W2T[i] = w2[c * 384 + j]; return; }
    i -= F;
    if (i < G) { int j = i / 128, c = i % 128; g_WgT[i] = wg2[c * 128 + j]; return; }
}

// ---------------- CSR build ----------------
__global__ void k_hist(const int* __restrict__ eidx) {
    int e = blockIdx.x * 256 + threadIdx.x;
    if (e < N_EDGES) atomicAdd(&g_deg[eidx[2 * e]], 1);
}

__global__ void k_assign() {
    __shared__ int wsum[8];
    __shared__ int sbase;
    int i = blockIdx.x * 256 + threadIdx.x;
    int d = (i < N_NODES) ? g_deg[i] : 0;
    int lane = threadIdx.x & 31, w = threadIdx.x >> 5;
    int p = d;
#pragma unroll
    for (int o = 1; o < 32; o <<= 1) {
        int v = __shfl_up_sync(0xffffffffu, p, o);
        if (lane >= o) p += v;
    }
    if (lane == 31) wsum[w] = p;
    __syncthreads();
    if (threadIdx.x == 0) {
        int s = 0;
#pragma unroll
        for (int k = 0; k < 8; k++) { int t = wsum[k]; wsum[k] = s; s += t; }
        sbase = atomicAdd(&g_ctr, s);
    }
    __syncthreads();
    int off = sbase + wsum[w] + p - d;
    if (i < N_NODES) { g_off[i] = off; g_pos[i] = off; }
}

__global__ void k_sort(const int* __restrict__ eidx, const float* __restrict__ etype) {
    int e = blockIdx.x * 256 + threadIdx.x;
    if (e < N_EDGES) {
        int f = eidx[2 * e], to = eidx[2 * e + 1];
        int slot = atomicAdd(&g_pos[f], 1);
        g_toS[slot] = to;
        g_efS[slot] = *(const float4*)(etype + 4 * e);
    }
}

// ---------------- f32x2 GEMM (op / skip / geo) ----------------
enum { XS_EXT = 0, XS_CF0 = 1, XS_CF1 = 2 };
enum { WS_OP = 0, WS_SKIP = 3, WS_GEO = 4 };
enum { YS_CF0 = 0 };

__device__ __forceinline__ const float* sel_x(int s, const float* ext) {
    if (s == XS_CF0) return g_cf0;
    if (s == XS_CF1) return g_cf1;
    return ext;
}
__device__ __forceinline__ const float* sel_w(int s) {
    switch (s) {
        case WS_OP:   return g_WopT;
        case WS_SKIP: return g_WskipT;
        default:      return g_WgeoT;
    }
}
__device__ __forceinline__ float* sel_y(int s) { (void)s; return g_cf0; }

template<int K, int COUT, bool STORE, bool HASBIAS, bool EXISTS, bool COLMAX>
__global__ void __launch_bounds__(256)
k_gemm(const float* __restrict__ Xext, int xsel, int wsel,
       const float* __restrict__ bias, const float* __restrict__ exists,
       int ysel, int slot) {
    constexpr int CH_T = COUT / 8;
    constexpr int ND_T = 256 / CH_T;
    constexpr int TN   = ND_T * 8;
    constexpr int XP   = TN + 2;
    constexpr int NKC  = (K + 31) / 32;

    __shared__ __align__(16) float sW[32 * COUT];
    __shared__ __align__(16) u64   sX2[32 * XP];
    __shared__ __align__(16) float sRed[COLMAX ? ND_T * COUT : 4];

    const float* X  = sel_x(xsel, Xext);
    const float* Wt = sel_w(wsel);

    int tid = threadIdx.x;
    int ct = tid % CH_T, nt = tid / CH_T;
    int nb = blockIdx.x * TN;

    u64* sW64 = reinterpret_cast<u64*>(sW);

    u64 acc2[4][8];
#pragma unroll
    for (int c = 0; c < 4; c++)
#pragma unroll
        for (int n = 0; n < 8; n++) acc2[c][n] = 0ull;

    for (int kc = 0; kc < NKC; kc++) {
        int k0 = kc * 32;
#pragma unroll
        for (int p = 0; p < COUT * 8 / 256; p++) {
            int idx4 = tid + p * 256;
            int c4 = idx4 % (COUT / 4), kk = idx4 / (COUT / 4);
            int k = k0 + kk;
            float4 wv = make_float4(0.f, 0.f, 0.f, 0.f);
            if (k < K) wv = *(const float4*)(Wt + k * COUT + c4 * 4);
            int c = c4 * 4;
            int ct0 = c >> 3;
            int j0  = (c & 7) >> 1;
            int base = kk * (COUT / 2) + ct0;
            sW64[base + j0 * CH_T]       = pack2(wv.x, wv.y);
            sW64[base + (j0 + 1) * CH_T] = pack2(wv.z, wv.w);
        }
        if (K % 32 == 0) {
#pragma unroll
            for (int p = 0; p < TN * 8 / 256; p++) {
                int idx4 = tid + p * 256;
                int kq = idx4 & 7, n = idx4 >> 3;
                int node = nb + n;
                float4 xv = make_float4(0.f, 0.f, 0.f, 0.f);
                if (node < N_NODES) xv = *(const float4*)(X + node * K + k0 + kq * 4);
                sX2[(kq * 4 + 0) * XP + n] = pack2(xv.x, xv.x);
                sX2[(kq * 4 + 1) * XP + n] = pack2(xv.y, xv.y);
                sX2[(kq * 4 + 2) * XP + n] = pack2(xv.z, xv.z);
                sX2[(kq * 4 + 3) * XP + n] = pack2(xv.w, xv.w);
            }
        } else {
#pragma unroll
            for (int p = 0; p < TN * 32 / 256; p++) {
                int idx = tid + p * 256;
                int kk = idx & 31, n = idx >> 5;
                int node = nb + n, k = k0 + kk;
                float v = (node < N_NODES && k < K) ? X[node * K + k] : 0.f;
                sX2[kk * XP + n] = pack2(v, v);
            }
        }
        __syncthreads();
#pragma unroll 8
        for (int kk = 0; kk < 32; kk++) {
            int wb = kk * (COUT / 2) + ct;
            u64 w_[4];
#pragma unroll
            for (int j = 0; j < 4; j++) w_[j] = sW64[wb + j * CH_T];
            const ulonglong2* xr = reinterpret_cast<const ulonglong2*>(sX2 + kk * XP + nt * 8);
            ulonglong2 xa = xr[0], xb = xr[1], xc = xr[2], xd = xr[3];
            u64 x_[8] = { xa.x, xa.y, xb.x, xb.y, xc.x, xc.y, xd.x, xd.y };
#pragma unroll
            for (int j = 0; j < 4; j++)
#pragma unroll
                for (int n = 0; n < 8; n++)
                    acc2[j][n] = fma2(w_[j], x_[n], acc2[j][n]);
        }
        __syncthreads();
    }

    float b[8];
#pragma unroll
    for (int c = 0; c < 8; c++) b[c] = HASBIAS ? bias[ct * 8 + c] : 0.f;
    float lmax[8];
#pragma unroll
    for (int c = 0; c < 8; c++) lmax[c] = -3.402823466e38f;

    float* Y = STORE ? sel_y(ysel) : nullptr;
#pragma unroll
    for (int n = 0; n < 8; n++) {
        int node = nb + nt * 8 + n;
        if (node < N_NODES) {
            float ex = EXISTS ? exists[node] : 1.f;
            float y[8];
#pragma unroll
            for (int cp = 0; cp < 4; cp++)
                unpack2(acc2[cp][n], y[2 * cp], y[2 * cp + 1]);
#pragma unroll
            for (int c = 0; c < 8; c++) {
                float v = y[c] + b[c];
                if (EXISTS) v *= ex;
                y[c] = v;
                if (COLMAX) lmax[c] = fmaxf(lmax[c], v);
            }
            if (STORE) {
                float4 y0 = { y[0], y[1], y[2], y[3] };
                float4 y1 = { y[4], y[5], y[6], y[7] };
                *(float4*)(Y + node * COUT + ct * 8)     = y0;
                *(float4*)(Y + node * COUT + ct * 8 + 4) = y1;
            }
        }
    }

    if (COLMAX) {
#pragma unroll
        for (int c = 0; c < 8; c++) sRed[nt * COUT + ct * 8 + c] = lmax[c];
        __syncthreads();
        for (int c = tid; c < COUT; c += 256) {
            float m = sRed[c];
#pragma unroll
            for (int r = 1; r < ND_T; r++) m = fmaxf(m, sRed[r * COUT + c]);
            atomicMax(&g_keys[slot * 128 + c], fkey(m));
        }
    }
}

// ---------------- mma.sync P-GEMM: P[64 nodes/block, 256] = cf @ Wp^T ----------------
// 2xBF16 split on HMMA: D = Ah*Bh + Ah*Bl + Al*Bh.
// Block = 256 thr = 8 warps: warp (w&3) -> 16-node sub-tile, (w>>2) -> 128-ch half.
__global__ void __launch_bounds__(256)
k_pgemm(int xsel, int it) {
    const float* X = xsel ? g_cf1 : g_cf0;
    int tid = threadIdx.x, w = tid >> 5, lane = tid & 31;
    int chhalf = w >> 2;
    int nb = blockIdx.x * 64 + (w & 3) * 16;
    int g = lane >> 2;                 // group id (row within 8)
    int tg = lane & 3;                 // thread in group
    int row0 = nb + g, row1 = nb + g + 8;
    bool v0 = row0 < N_NODES, v1 = row1 < N_NODES;
    const float* x0 = X + (v0 ? row0 : 0) * 128;
    const float* x1 = X + (v1 ? row1 : 0) * 128;
    const uint32_t* Bh = g_Bf[it][0] + ((chhalf * 16) * 32 + lane) * 2;
    const uint32_t* Bl = g_Bf[it][1] + ((chhalf * 16) * 32 + lane) * 2;

    float acc[16][4];
#pragma unroll
    for (int t = 0; t < 16; t++)
#pragma unroll
        for (int q = 0; q < 4; q++) acc[t][q] = 0.f;

#pragma unroll
    for (int s = 0; s < 8; s++) {
        int kb = s * 16 + tg * 2;
        float2 p00 = *(const float2*)(x0 + kb);
        float2 p01 = *(const float2*)(x0 + kb + 8);
        float2 p10 = *(const float2*)(x1 + kb);
        float2 p11 = *(const float2*)(x1 + kb + 8);
        uint32_t ah[4], al[4];
        bsplit2(p00.x, p00.y, ah[0], al[0]);
        bsplit2(p10.x, p10.y, ah[1], al[1]);
        bsplit2(p01.x, p01.y, ah[2], al[2]);
        bsplit2(p11.x, p11.y, ah[3], al[3]);
        const uint32_t* bhp = Bh + s * 2048;    // s stride = 32 tiles * 32 lanes * 2
        const uint32_t* blp = Bl + s * 2048;
#pragma unroll
        for (int t = 0; t < 16; t++) {
            uint2 bh = *(const uint2*)(bhp + t * 64);
            uint2 bl = *(const uint2*)(blp + t * 64);
            mma16816(acc[t], ah, bh.x, bh.y);
            mma16816(acc[t], ah, bl.x, bl.y);
            mma16816(acc[t], al, bh.x, bh.y);
        }
    }

    // store: lane covers cols chhalf*128 + t*8 + tg*2 (+1), rows row0 / row1
    int chb = chhalf * 128 + tg * 2;
#pragma unroll
    for (int t = 0; t < 16; t++) {
        int ch = chb + t * 8;
        if (v0) *(float2*)(g_P + row0 * 256 + ch) = make_float2(acc[t][0], acc[t][1]);
        if (v1) *(float2*)(g_P + row1 * 256 + ch) = make_float2(acc[t][2], acc[t][3]);
    }
}

// ---------------- per-node gather + max, dynamically load-balanced ----------------
template<bool STORE>
__global__ void __launch_bounds__(512)
k_edge(const float* __restrict__ eb, int wesel, int slot) {
    const float* WeP = wesel ? g_WeP1 : g_WeP0;
    int warp = threadIdx.x >> 5, lane = threadIdx.x & 31;
    __shared__ __align__(16) float sRed[16 * 128];

    const float4* P4 = (const float4*)g_P;
    float4 b4 = *(const float4*)(eb + lane * 4);
    const float4* We4 = (const float4*)WeP;
    float4 we0 = We4[lane * 4 + 0];
    float4 we1 = We4[lane * 4 + 1];
    float4 we2 = We4[lane * 4 + 2];
    float4 we3 = We4[lane * 4 + 3];

    float4 cmax = make_float4(-3.402823466e38f, -3.402823466e38f,
                              -3.402823466e38f, -3.402823466e38f);
    for (;;) {
        int v0 = 0;
        if (lane == 0) v0 = atomicAdd(&g_work[wesel], 2);
        v0 = __shfl_sync(0xffffffffu, v0, 0);
        if (v0 >= N_NODES) break;
        int vend = (v0 + 2 < N_NODES) ? v0 + 2 : N_NODES;
        for (int v = v0; v < vend; v++) {
            float4 pa = P4[v * 64 + lane];
            float4 base = { pa.x + b4.x, pa.y + b4.y, pa.z + b4.z, pa.w + b4.w };
            int start = g_off[v], deg = g_deg[v];
            float4 acc = make_float4(0.f, 0.f, 0.f, 0.f);
#pragma unroll 4
            for (int j = 0; j < deg; j++) {
                int to = g_toS[start + j];
                float4 ef = g_efS[start + j];
                float4 pb = P4[to * 64 + 32 + lane];
                float d0 = fmaf(we0.x, ef.x, fmaf(we0.y, ef.y, fmaf(we0.z, ef.z, we0.w * ef.w)));
                float d1 = fmaf(we1.x, ef.x, fmaf(we1.y, ef.y, fmaf(we1.z, ef.z, we1.w * ef.w)));
                float d2 = fmaf(we2.x, ef.x, fmaf(we2.y, ef.y, fmaf(we2.z, ef.z, we2.w * ef.w)));
                float d3 = fmaf(we3.x, ef.x, fmaf(we3.y, ef.y, fmaf(we3.z, ef.z, we3.w * ef.w)));
                float v0f = base.x + pb.x + d0;
                float v1f = base.y + pb.y + d1;
                float v2f = base.z + pb.z + d2;
                float v3f = base.w + pb.w + d3;
                acc.x = fmaxf(acc.x, fmaxf(v0f, 0.01f * v0f));
                acc.y = fmaxf(acc.y, fmaxf(v1f, 0.01f * v1f));
                acc.z = fmaxf(acc.z, fmaxf(v2f, 0.01f * v2f));
                acc.w = fmaxf(acc.w, fmaxf(v3f, 0.01f * v3f));
            }
            if (STORE) *(float4*)(g_cf1 + v * 128 + lane * 4) = acc;
            cmax.x = fmaxf(cmax.x, acc.x);
            cmax.y = fmaxf(cmax.y, acc.y);
            cmax.z = fmaxf(cmax.z, acc.z);
            cmax.w = fmaxf(cmax.w, acc.w);
        }
    }
    *(float4*)(sRed + warp * 128 + lane * 4) = cmax;
    __syncthreads();
    int t = threadIdx.x;
    if (t < 128) {
        float m = sRed[t];
#pragma unroll
        for (int r = 1; r < 16; r++) m = fmaxf(m, sRed[r * 128 + t]);
        atomicMax(&g_keys[slot * 128 + t], fkey(m));
    }
}

// ---------------- finalize: tiny GEMMs + group norm ----------------
__global__ void __launch_bounds__(384)
k_final(const float* __restrict__ second_b, const float* __restrict__ sgeo_b,
        const float* __restrict__ gnw, const float* __restrict__ gnb,
        float* __restrict__ out) {
    __shared__ float spf[384];
    __shared__ float spg[128];
    int t = threadIdx.x;
    if (t < 384) spf[t] = fdec(g_keys[t]);
    if (t < 128) spg[t] = leaky(fdec(g_keys[512 + t]));
    __syncthreads();
    if (t < 128) {
        float a = 0.f;
#pragma unroll 4
        for (int j = 0; j < 384; j++) a = fmaf(spf[j], g_W2T[j * 128 + t], a);
        a += second_b[t];
        out[t] = leaky(a);

        float g = 0.f;
#pragma unroll 4
        for (int j = 0; j < 128; j++) g = fmaf(spg[j], g_WgT[j * 128 + t], g);
        g += sgeo_b[t];

        float s = g;
        s += __shfl_xor_sync(0xffffffffu, s, 1, 8);
        s += __shfl_xor_sync(0xffffffffu, s, 2, 8);
        s += __shfl_xor_sync(0xffffffffu, s, 4, 8);
        float mu = s * 0.125f;
        float d = g - mu;
        float q = d * d;
        q += __shfl_xor_sync(0xffffffffu, q, 1, 8);
        q += __shfl_xor_sync(0xffffffffu, q, 2, 8);
        q += __shfl_xor_sync(0xffffffffu, q, 4, 8);
        float var = q * 0.125f;
        float xn = d * rsqrtf(var + 1e-5f);
        float y = xn * gnw[t] + gnb[t];
        float sgv = fdec(g_keys[384 + t]);
        float o = leaky(sgv) + y;
        out[128 + t] = leaky(o);
    }
}

// ---------------- host launcher ----------------
static cudaStream_t s_csr = 0, s_geo = 0;
static cudaEvent_t evInit = 0, evPrep = 0, evCsr = 0, evGeo = 0;

extern "C" void kernel_launch(void* const* d_in, const int* in_sizes, int n_in,
                              void* d_out, int out_size) {
    const float* child_feats = (const float*)d_in[0];
    const float* child_geo   = (const float*)d_in[1];
    const float* exists      = (const float*)d_in[2];
    const float* etype       = (const float*)d_in[3];
    const int*   eidx        = (const int*)d_in[4];
    const float* wop   = (const float*)d_in[5];
    const float* bop   = (const float*)d_in[6];
    const float* w2    = (const float*)d_in[7];
    const float* b2    = (const float*)d_in[8];
    const float* ew    = (const float*)d_in[9];
    const float* ebias = (const float*)d_in[10];
    const float* wgeo  = (const float*)d_in[11];
    const float* bgeo  = (const float*)d_in[12];
    const float* wg2   = (const float*)d_in[13];
    const float* bg2   = (const float*)d_in[14];
    const float* gnw   = (const float*)d_in[15];
    const float* gnb   = (const float*)d_in[16];
    const float* wskip = (const float*)d_in[17];
    const float* bskip = (const float*)d_in[18];
    float* out = (float*)d_out;

    (void)in_sizes; (void)n_in; (void)out_size;

    if (!s_csr) {
        cudaStreamCreateWithFlags(&s_csr, cudaStreamNonBlocking);
        cudaStreamCreateWithFlags(&s_geo, cudaStreamNonBlocking);
        cudaEventCreateWithFlags(&evInit, cudaEventDisableTiming);
        cudaEventCreateWithFlags(&evPrep, cudaEventDisableTiming);
        cudaEventCreateWithFlags(&evCsr,  cudaEventDisableTiming);
        cudaEventCreateWithFlags(&evGeo,  cudaEventDisableTiming);
    }

    // main stream: init + weight packing
    k_init<<<(N_NODES + 255) / 256, 256>>>();
    cudaEventRecord(evInit, 0);
    {
        const int total = FIN * 128 + 2 * 16384 + 2 * 128 * 4
                        + 128 * 128 + 128 * 128 + 384 * 128 + 128 * 128;
        k_prep<<<(total + 255) / 256, 256>>>(wop, ew, wskip, wgeo, w2, wg2);
    }
    cudaEventRecord(evPrep, 0);

    // CSR stream
    cudaStreamWaitEvent(s_csr, evInit, 0);
    k_hist<<<(N_EDGES + 255) / 256, 256, 0, s_csr>>>(eidx);
    k_assign<<<(N_NODES + 255) / 256, 256, 0, s_csr>>>();
    k_sort<<<(N_EDGES + 255) / 256, 256, 0, s_csr>>>(eidx, etype);
    cudaEventRecord(evCsr, s_csr);

    // geo stream
    cudaStreamWaitEvent(s_geo, evPrep, 0);
    k_gemm<128, 128, false, true, true, true><<<(N_NODES + 127) / 128, 256, 0, s_geo>>>(
        child_geo, XS_EXT, WS_SKIP, bskip, exists, YS_CF0, 3);
    k_gemm<128, 128, false, true, true, true><<<(N_NODES + 127) / 128, 256, 0, s_geo>>>(
        child_geo, XS_EXT, WS_GEO, bgeo, exists, YS_CF0, 4);
    cudaEventRecord(evGeo, s_geo);

    // main chain
    k_gemm<FIN, 128, true, true, true, true><<<(N_NODES + 127) / 128, 256>>>(
        child_feats, XS_EXT, WS_OP, bop, exists, YS_CF0, 0);

    // iteration 0
    k_pgemm<<<(N_NODES + 63) / 64, 256>>>(0, 0);
    cudaStreamWaitEvent(0, evCsr, 0);
    k_edge<true><<<296, 512>>>(ebias, 0, 1);

    // iteration 1
    k_pgemm<<<(N_NODES + 63) / 64, 256>>>(1, 1);
    k_edge<false><<<296, 512>>>(ebias + 128, 1, 2);

    // finalize
    cudaStreamWaitEvent(0, evGeo, 0);
    k_final<<<1, 384>>>(b2, bg2, gnw, gnb, out);
}